// round 8
// baseline (speedup 1.0000x reference)
#include <cuda_runtime.h>
#include <cuda_fp16.h>
#include <math.h>
#include <stdint.h>

#define NN_NODE 10000
#define E_NUM   320000
#define FDIM    256
#define NLAYERS 5
#define OC      128
#define KTOT    (NLAYERS*FDIM)   // 1280

// ---------------- scratch ----------------
__device__ float g_dinv[2][NN_NODE];
__device__ int   g_cnt[2][NN_NODE];
__device__ int   g_rowptr[2][NN_NODE + 1];
__device__ int   g_csr_src[2][E_NUM];
__device__ float g_csr_norm[2][E_NUM];
__device__ __align__(16) __half g_feats[2][(size_t)NN_NODE * KTOT];     // fp16 activations
__device__ __align__(16) __half g_t[2][(size_t)NN_NODE * FDIM];         // fp16 aggregated
__device__ __align__(16) __half g_xh[2][(size_t)NN_NODE * FDIM];        // fp16 inputs
__device__ __align__(16) __half g_wt[2][(size_t)NLAYERS * FDIM * FDIM]; // fp16 W^T
__device__ float g_amax[2][NLAYERS];
__device__ float g_atts[2][NLAYERS];
__device__ __align__(16) __half g_weff[2][OC * KTOT];
__device__ __align__(16) __half g_emb[2][(size_t)NN_NODE * OC];

// ---------------- FP16 cp.async GEMM 128x128x32, 3-stage, branch-batched ----------------
// C = A @ B^T.  A [M,K] half rm, B [N,K] half rm. K multiple of 32.
#define MMA_F16(d, a, b) \
  asm volatile("mma.sync.aligned.m16n8k16.row.col.f32.f16.f16.f32 " \
      "{%0,%1,%2,%3}, {%4,%5,%6,%7}, {%8,%9}, {%0,%1,%2,%3};" \
      : "+f"(d[0]), "+f"(d[1]), "+f"(d[2]), "+f"(d[3]) \
      : "r"(a[0]), "r"(a[1]), "r"(a[2]), "r"(a[3]), "r"(b[0]), "r"(b[1]))

__device__ __forceinline__ void cp16(uint32_t d, const void* s, bool p) {
    int sz = p ? 16 : 0;
    asm volatile("cp.async.cg.shared.global [%0], [%1], 16, %2;\n" :: "r"(d), "l"(s), "r"(sz));
}
__device__ __forceinline__ void cp_commit() { asm volatile("cp.async.commit_group;\n"); }
template <int N> __device__ __forceinline__ void cp_wait() {
    asm volatile("cp.async.wait_group %0;\n" :: "n"(N));
}

// LAYER_EPI: relu(acc+bias), half store, fused global-max into g_amax[bz][layer]
template <int BIAS, int OUT_HALF, int STREAM_OUT, int LAYER_EPI>
__global__ __launch_bounds__(256) void k_gemm_f16(
        int M, int N, int K,
        const __half* __restrict__ A0, const __half* __restrict__ A1, int lda,
        const __half* __restrict__ B0, const __half* __restrict__ B1, int ldb,
        void* __restrict__ C0, void* __restrict__ C1, int ldc,
        const float* __restrict__ bias0, const float* __restrict__ bias1, int layer) {
    constexpr int STAGES = 3;
    constexpr int LD32 = 20;            // 32 halves + 8 pad = 40 halves = 20 u32
    constexpr int A_ST = 128 * LD32;
    constexpr int B_ST = 128 * LD32;
    extern __shared__ uint32_t smem[];
    uint32_t* As = smem;
    uint32_t* Bs = smem + STAGES * A_ST;

    const int bz = blockIdx.z;
    const __half* A = bz ? A1 : A0;
    const __half* B = bz ? B1 : B0;
    void* Cv = bz ? C1 : C0;
    const float* bias = bz ? bias1 : bias0;

    const int tid = threadIdx.x;
    const int wid = tid >> 5;
    const int lane = tid & 31;
    const int g = lane >> 2, t = lane & 3;
    const int wm = wid >> 1, wn = wid & 1;
    const int i0 = blockIdx.y * 128, j0 = blockIdx.x * 128;

    const int ar = tid >> 1, akc = (tid & 1) * 16;   // row, half-offset

    const bool a_ok = (i0 + ar < M);
    const __half* a_src = A + (size_t)(a_ok ? i0 + ar : M - 1) * lda + akc;
    const bool b_ok = (j0 + ar < N);
    const __half* b_src = B + (size_t)(b_ok ? j0 + ar : N - 1) * ldb + akc;

    uint32_t sa_base = (uint32_t)__cvta_generic_to_shared(&As[ar * LD32 + akc / 2]);
    uint32_t sb_base = (uint32_t)__cvta_generic_to_shared(&Bs[ar * LD32 + akc / 2]);

    auto issue = [&](int s, int k0) {
        uint32_t da = sa_base + s * (A_ST * 4);
        const __half* pa = a_src + k0;
        cp16(da,      pa,     a_ok);
        cp16(da + 16, pa + 8, a_ok);
        uint32_t db = sb_base + s * (B_ST * 4);
        const __half* pb = b_src + k0;
        cp16(db,      pb,     b_ok);
        cp16(db + 16, pb + 8, b_ok);
        cp_commit();
    };

    float acc[2][8][4];
    #pragma unroll
    for (int mt = 0; mt < 2; mt++)
        #pragma unroll
        for (int nt = 0; nt < 8; nt++)
            #pragma unroll
            for (int q = 0; q < 4; q++) acc[mt][nt][q] = 0.0f;

    auto compute = [&](int s) {
        const uint32_t* Ab = As + s * A_ST;
        const uint32_t* Bb = Bs + s * B_ST;
        #pragma unroll
        for (int c = 0; c < 2; c++) {
            const int base = c * 8;
            uint32_t af[2][4];
            #pragma unroll
            for (int mt = 0; mt < 2; mt++) {
                int r = wm * 32 + mt * 16;
                af[mt][0] = Ab[(r + g) * LD32 + base + t];
                af[mt][1] = Ab[(r + g + 8) * LD32 + base + t];
                af[mt][2] = Ab[(r + g) * LD32 + base + t + 4];
                af[mt][3] = Ab[(r + g + 8) * LD32 + base + t + 4];
            }
            uint32_t bf[8][2];
            #pragma unroll
            for (int nt = 0; nt < 8; nt++) {
                int n = wn * 64 + nt * 8 + g;
                bf[nt][0] = Bb[n * LD32 + base + t];
                bf[nt][1] = Bb[n * LD32 + base + t + 4];
            }
            #pragma unroll
            for (int mt = 0; mt < 2; mt++)
                #pragma unroll
                for (int nt = 0; nt < 8; nt++)
                    MMA_F16(acc[mt][nt], af[mt], bf[nt]);
        }
    };

    const int ktiles = K / 32;
    issue(0, 0);
    if (ktiles > 1) issue(1, 32);
    for (int i = 0; i < ktiles; i++) {
        // committed = min(i+2, ktiles); compute(i) needs group i done.
        // Last iteration: committed == i+1 -> must drain fully.
        if (i < ktiles - 1) cp_wait<STAGES - 2>(); else cp_wait<0>();
        __syncthreads();
        int pf = i + STAGES - 1;
        if (pf < ktiles) issue(pf % STAGES, pf * 32);
        compute(i % STAGES);
    }

    float tmax = 0.0f;
    #pragma unroll
    for (int mt = 0; mt < 2; mt++) {
        int r0 = i0 + wm * 32 + mt * 16 + g;
        #pragma unroll
        for (int nt = 0; nt < 8; nt++) {
            int c = j0 + wn * 64 + nt * 8 + 2 * t;
            if (c >= N) continue;
            float bx0 = 0.f, bx1 = 0.f;
            if (BIAS || LAYER_EPI) { bx0 = bias[c]; bx1 = bias[c + 1]; }
            float v00 = acc[mt][nt][0] + bx0, v01 = acc[mt][nt][1] + bx1;
            float v10 = acc[mt][nt][2] + bx0, v11 = acc[mt][nt][3] + bx1;
            if (LAYER_EPI) {
                v00 = fmaxf(v00, 0.f); v01 = fmaxf(v01, 0.f);
                v10 = fmaxf(v10, 0.f); v11 = fmaxf(v11, 0.f);
                if (r0 < M)     tmax = fmaxf(tmax, fmaxf(v00, v01));
                if (r0 + 8 < M) tmax = fmaxf(tmax, fmaxf(v10, v11));
            }
            if (OUT_HALF) {
                __half* Ch = (__half*)Cv;
                __half2 h0 = __float22half2_rn(make_float2(v00, v01));
                __half2 h1 = __float22half2_rn(make_float2(v10, v11));
                if (r0 < M)     *(__half2*)(Ch + (size_t)r0 * ldc + c) = h0;
                if (r0 + 8 < M) *(__half2*)(Ch + (size_t)(r0 + 8) * ldc + c) = h1;
            } else {
                float* Cf = (float*)Cv;
                float2 p0 = make_float2(v00, v01);
                float2 p1 = make_float2(v10, v11);
                if (STREAM_OUT) {
                    if (r0 < M)     __stcs((float2*)(Cf + (size_t)r0 * ldc + c), p0);
                    if (r0 + 8 < M) __stcs((float2*)(Cf + (size_t)(r0 + 8) * ldc + c), p1);
                } else {
                    if (r0 < M)     *(float2*)(Cf + (size_t)r0 * ldc + c) = p0;
                    if (r0 + 8 < M) *(float2*)(Cf + (size_t)(r0 + 8) * ldc + c) = p1;
                }
            }
        }
    }

    if (LAYER_EPI) {
        #pragma unroll
        for (int off = 16; off > 0; off >>= 1)
            tmax = fmaxf(tmax, __shfl_xor_sync(0xffffffffu, tmax, off));
        __syncthreads();                     // smem no longer needed for tiles
        float* red = (float*)smem;
        if (lane == 0) red[wid] = tmax;
        __syncthreads();
        if (tid == 0) {
            float m = red[0];
            #pragma unroll
            for (int q = 1; q < 8; q++) m = fmaxf(m, red[q]);
            atomicMax((int*)&g_amax[bz][layer], __float_as_int(m));
        }
    }
}

// ---------------- func attrs set once ----------------
struct HxRes {
    HxRes() {
        cudaFuncSetAttribute((const void*)k_gemm_f16<0,1,0,1>, cudaFuncAttributeMaxDynamicSharedMemorySize, 65536);
        cudaFuncSetAttribute((const void*)k_gemm_f16<1,1,0,0>, cudaFuncAttributeMaxDynamicSharedMemorySize, 65536);
        cudaFuncSetAttribute((const void*)k_gemm_f16<0,0,1,0>, cudaFuncAttributeMaxDynamicSharedMemorySize, 65536);
    }
};
static HxRes g_hx;

// ---------------- prep kernels (branch-batched via grid.y) ----------------
__global__ void k_init() {
    int i = blockIdx.x * blockDim.x + threadIdx.x;
    if (i < NN_NODE) {
        g_dinv[0][i] = 1.0f; g_dinv[1][i] = 1.0f;
        g_cnt[0][i] = 0;     g_cnt[1][i] = 0;
    }
    if (i < NLAYERS) { g_amax[0][i] = 0.0f; g_amax[1][i] = 0.0f; }
}

__global__ void k_halfcpy_b(const float* __restrict__ in0, const float* __restrict__ in1,
                            int n4) {
    int b = blockIdx.y;
    const float* in = b ? in1 : in0;
    __half* out = g_xh[b];
    int i = blockIdx.x * blockDim.x + threadIdx.x;
    if (i < n4) {
        float4 v = ((const float4*)in)[i];
        __half2 h0 = __float22half2_rn(make_float2(v.x, v.y));
        __half2 h1 = __float22half2_rn(make_float2(v.z, v.w));
        ((uint2*)out)[i] = make_uint2(*(uint32_t*)&h0, *(uint32_t*)&h1);
    }
}

// W [L][K][N] f32 -> W^T [L][N][K] half
__global__ void k_halfT_b(const float* __restrict__ in0, const float* __restrict__ in1,
                          int total) {
    int b = blockIdx.y;
    const float* in = b ? in1 : in0;
    __half* out = g_wt[b];
    int idx = blockIdx.x * blockDim.x + threadIdx.x;
    if (idx < total) {
        int l = idx >> 16;
        int rem = idx & 65535;
        int k = rem >> 8, n = rem & 255;
        out[(size_t)l * 65536 + n * 256 + k] = __float2half(in[idx]);
    }
}

__global__ void k_deg_cnt_b(const int* __restrict__ e0, const int* __restrict__ e1,
                            const float* __restrict__ w0, const float* __restrict__ w1) {
    int b = blockIdx.y;
    const int* edges = b ? e1 : e0;
    const float* w = b ? w1 : w0;
    int e = blockIdx.x * blockDim.x + threadIdx.x;
    if (e < E_NUM) {
        int dst = edges[E_NUM + e];
        atomicAdd(&g_dinv[b][dst], w[e]);
        atomicAdd(&g_cnt[b][dst], 1);
    }
}

// scan (+ fused rsqrt); one block per branch
__global__ void k_scan() {
    int b = blockIdx.x;
    __shared__ int wsum[32];
    __shared__ int chunk_base;
    int tid = threadIdx.x, lane = tid & 31, w = tid >> 5;
    if (tid == 0) chunk_base = 0;
    __syncthreads();
    for (int c0 = 0; c0 < NN_NODE; c0 += 1024) {
        int idx = c0 + tid;
        int v = (idx < NN_NODE) ? g_cnt[b][idx] : 0;
        if (idx < NN_NODE) g_dinv[b][idx] = rsqrtf(g_dinv[b][idx]);
        int sc = v;
        #pragma unroll
        for (int off = 1; off < 32; off <<= 1) {
            int u = __shfl_up_sync(0xffffffffu, sc, off);
            if (lane >= off) sc += u;
        }
        if (lane == 31) wsum[w] = sc;
        __syncthreads();
        if (w == 0) {
            int tv = wsum[lane];
            #pragma unroll
            for (int off = 1; off < 32; off <<= 1) {
                int u = __shfl_up_sync(0xffffffffu, tv, off);
                if (lane >= off) tv += u;
            }
            wsum[lane] = tv;
        }
        __syncthreads();
        int total = wsum[31];
        int excl = chunk_base + (w ? wsum[w - 1] : 0) + sc - v;
        if (idx < NN_NODE) { g_rowptr[b][idx] = excl; g_cnt[b][idx] = 0; }
        __syncthreads();
        if (tid == 0) chunk_base += total;
        __syncthreads();
    }
    if (tid == 0) g_rowptr[b][NN_NODE] = chunk_base;
}

__global__ void k_fill_b(const int* __restrict__ e0, const int* __restrict__ e1,
                         const float* __restrict__ w0, const float* __restrict__ w1) {
    int b = blockIdx.y;
    const int* edges = b ? e1 : e0;
    const float* w = b ? w1 : w0;
    int e = blockIdx.x * blockDim.x + threadIdx.x;
    if (e < E_NUM) {
        int s = edges[e];
        int d = edges[E_NUM + e];
        int pos = g_rowptr[b][d] + atomicAdd(&g_cnt[b][d], 1);
        g_csr_src[b][pos] = s;
        g_csr_norm[b][pos] = g_dinv[b][s] * w[e] * g_dinv[b][d];
    }
}

// ---------------- pure gather-aggregation (agg-first): t = D^-1/2 (A+I) D^-1/2 @ in ----------------
__global__ __launch_bounds__(64) void k_agg(const __half* __restrict__ in0,
                                            const __half* __restrict__ in1, int ld) {
    int b = blockIdx.y;
    int v = blockIdx.x;
    int t = threadIdx.x;                 // 0..63, 4 halves each
    const __half* in = b ? in1 : in0;
    float dv = g_dinv[b][v];
    float sw = dv * dv;

    uint2 raw = *(const uint2*)(in + (size_t)v * ld + t * 4);
    float2 a01 = __half22float2(*(__half2*)&raw.x);
    float2 a23 = __half22float2(*(__half2*)&raw.y);
    float4 acc = make_float4(sw * a01.x, sw * a01.y, sw * a23.x, sw * a23.y);

    int e = g_rowptr[b][v];
    int e2 = g_rowptr[b][v + 1];
    const int*   srcs  = g_csr_src[b];
    const float* norms = g_csr_norm[b];
    for (; e + 4 <= e2; e += 4) {
        int u0 = srcs[e], u1 = srcs[e + 1], u2 = srcs[e + 2], u3 = srcs[e + 3];
        float n0 = norms[e], n1 = norms[e + 1], n2 = norms[e + 2], n3 = norms[e + 3];
        uint2 r0 = *(const uint2*)(in + (size_t)u0 * ld + t * 4);
        uint2 r1 = *(const uint2*)(in + (size_t)u1 * ld + t * 4);
        uint2 r2 = *(const uint2*)(in + (size_t)u2 * ld + t * 4);
        uint2 r3 = *(const uint2*)(in + (size_t)u3 * ld + t * 4);
        float2 x0a = __half22float2(*(__half2*)&r0.x), x0b = __half22float2(*(__half2*)&r0.y);
        float2 x1a = __half22float2(*(__half2*)&r1.x), x1b = __half22float2(*(__half2*)&r1.y);
        float2 x2a = __half22float2(*(__half2*)&r2.x), x2b = __half22float2(*(__half2*)&r2.y);
        float2 x3a = __half22float2(*(__half2*)&r3.x), x3b = __half22float2(*(__half2*)&r3.y);
        acc.x += n0 * x0a.x + n1 * x1a.x + n2 * x2a.x + n3 * x3a.x;
        acc.y += n0 * x0a.y + n1 * x1a.y + n2 * x2a.y + n3 * x3a.y;
        acc.z += n0 * x0b.x + n1 * x1b.x + n2 * x2b.x + n3 * x3b.x;
        acc.w += n0 * x0b.y + n1 * x1b.y + n2 * x2b.y + n3 * x3b.y;
    }
    for (; e < e2; e++) {
        float n = norms[e];
        uint2 r = *(const uint2*)(in + (size_t)srcs[e] * ld + t * 4);
        float2 xa = __half22float2(*(__half2*)&r.x), xb = __half22float2(*(__half2*)&r.y);
        acc.x += n * xa.x; acc.y += n * xa.y; acc.z += n * xb.x; acc.w += n * xb.y;
    }
    __half2 h0 = __float22half2_rn(make_float2(acc.x, acc.y));
    __half2 h1p = __float22half2_rn(make_float2(acc.z, acc.w));
    *(uint2*)&g_t[b][(size_t)v * FDIM + t * 4] =
        make_uint2(*(uint32_t*)&h0, *(uint32_t*)&h1p);
}

// ---------------- attention FC + effective conv weights ----------------
__global__ void k_attfc(const float* __restrict__ f1w0, const float* __restrict__ f1b0,
                        const float* __restrict__ f2w0, const float* __restrict__ f2b0,
                        const float* __restrict__ f1w1, const float* __restrict__ f1b1,
                        const float* __restrict__ f2w1, const float* __restrict__ f2b1) {
    int b = blockIdx.x;
    const float* fc1w = b ? f1w1 : f1w0;
    const float* fc1b = b ? f1b1 : f1b0;
    const float* fc2w = b ? f2w1 : f2w0;
    const float* fc2b = b ? f2b1 : f2b0;
    if (threadIdx.x == 0) {
        float a[NLAYERS];
        for (int c = 0; c < NLAYERS; c++) a[c] = g_amax[b][c];
        float t[5 * NLAYERS];
        for (int j = 0; j < 5 * NLAYERS; j++) {
            float s = fc1b[j];
            for (int c = 0; c < NLAYERS; c++) s += fc1w[j * NLAYERS + c] * a[c];
            t[j] = fmaxf(s, 0.f);
        }
        for (int c = 0; c < NLAYERS; c++) {
            float s = fc2b[c];
            for (int j = 0; j < 5 * NLAYERS; j++) s += fc2w[c * (5 * NLAYERS) + j] * t[j];
            g_atts[b][c] = 1.0f / (1.0f + expf(-s));
        }
    }
}

__global__ void k_weff_b(const float* __restrict__ cw0, const float* __restrict__ cw1) {
    int b = blockIdx.y;
    const float* cw = b ? cw1 : cw0;
    int idx = blockIdx.x * blockDim.x + threadIdx.x;
    if (idx < OC * KTOT) {
        int c = (idx % KTOT) >> 8;
        g_weff[b][idx] = __float2half(cw[idx] * g_atts[b][c]);
    }
}

// ---------------- launch ----------------
extern "C" void kernel_launch(void* const* d_in, const int* in_sizes, int n_in,
                              void* d_out, int out_size) {
    const float* x_m    = (const float*)d_in[0];
    const float* x_d    = (const float*)d_in[1];
    const float* w_m    = (const float*)d_in[2];
    const float* w_d    = (const float*)d_in[3];
    const float* Wx     = (const float*)d_in[4];
    const float* bx     = (const float*)d_in[5];
    const float* Wy     = (const float*)d_in[6];
    const float* by     = (const float*)d_in[7];
    const float* fc1x_w = (const float*)d_in[8];
    const float* fc1x_b = (const float*)d_in[9];
    const float* fc2x_w = (const float*)d_in[10];
    const float* fc2x_b = (const float*)d_in[11];
    const float* fc1y_w = (const float*)d_in[12];
    const float* fc1y_b = (const float*)d_in[13];
    const float* fc2y_w = (const float*)d_in[14];
    const float* fc2y_b = (const float*)d_in[15];
    const float* cnnx_w = (const float*)d_in[16];
    const float* cnnx_b = (const float*)d_in[17];
    const float* cnny_w = (const float*)d_in[18];
    const float* cnny_b = (const float*)d_in[19];
    const int*   edges_m = (const int*)d_in[20];
    const int*   edges_d = (const int*)d_in[21];
    float* out = (float*)d_out;

    __half *p_feats, *p_t, *p_xh, *p_wt, *p_weff, *p_emb;
    cudaGetSymbolAddress((void**)&p_feats, g_feats);
    cudaGetSymbolAddress((void**)&p_t,     g_t);
    cudaGetSymbolAddress((void**)&p_xh,    g_xh);
    cudaGetSymbolAddress((void**)&p_wt,    g_wt);
    cudaGetSymbolAddress((void**)&p_weff,  g_weff);
    cudaGetSymbolAddress((void**)&p_emb,   g_emb);

    __half* feats0 = p_feats;
    __half* feats1 = p_feats + (size_t)NN_NODE * KTOT;
    __half* t0     = p_t;
    __half* t1     = p_t + (size_t)NN_NODE * FDIM;
    __half* xh0    = p_xh;
    __half* xh1    = p_xh + (size_t)NN_NODE * FDIM;
    __half* wt0    = p_wt;
    __half* wt1    = p_wt + (size_t)NLAYERS * FDIM * FDIM;
    __half* weff0  = p_weff;
    __half* weff1  = p_weff + (size_t)OC * KTOT;
    __half* emb0   = p_emb;
    __half* emb1   = p_emb + (size_t)NN_NODE * OC;

    const int MT = (NN_NODE + 127) / 128;   // 79
    const int SM_F16 = 3 * (128 * 20 + 128 * 20) * 4;  // 61440

    k_init<<<(NN_NODE + 255) / 256, 256>>>();
    k_halfcpy_b<<<dim3((NN_NODE * FDIM / 4 + 255) / 256, 2), 256>>>(x_m, x_d, NN_NODE * FDIM / 4);
    k_halfT_b<<<dim3((NLAYERS * FDIM * FDIM + 255) / 256, 2), 256>>>(Wx, Wy, NLAYERS * FDIM * FDIM);
    k_deg_cnt_b<<<dim3(E_NUM / 256, 2), 256>>>(edges_m, edges_d, w_m, w_d);
    k_scan<<<2, 1024>>>();
    k_fill_b<<<dim3(E_NUM / 256, 2), 256>>>(edges_m, edges_d, w_m, w_d);

    for (int i = 0; i < NLAYERS; i++) {
        const __half* in0 = i == 0 ? xh0 : feats0 + (size_t)(i - 1) * FDIM;
        const __half* in1 = i == 0 ? xh1 : feats1 + (size_t)(i - 1) * FDIM;
        int ld = i == 0 ? FDIM : KTOT;
        k_agg<<<dim3(NN_NODE, 2), 64>>>(in0, in1, ld);
        k_gemm_f16<0, 1, 0, 1><<<dim3(FDIM / 128, MT, 2), 256, SM_F16>>>(
            NN_NODE, FDIM, FDIM,
            t0, t1, FDIM,
            wt0 + (size_t)i * FDIM * FDIM, wt1 + (size_t)i * FDIM * FDIM, FDIM,
            feats0 + (size_t)i * FDIM, feats1 + (size_t)i * FDIM, KTOT,
            bx + (size_t)i * FDIM, by + (size_t)i * FDIM, i);
    }

    k_attfc<<<2, 32>>>(fc1x_w, fc1x_b, fc2x_w, fc2x_b,
                       fc1y_w, fc1y_b, fc2y_w, fc2y_b);
    k_weff_b<<<dim3((OC * KTOT + 255) / 256, 2), 256>>>(cnnx_w, cnny_w);

    k_gemm_f16<1, 1, 0, 0><<<dim3(1, MT, 2), 256, SM_F16>>>(
        NN_NODE, OC, KTOT,
        feats0, feats1, KTOT,
        weff0, weff1, KTOT,
        emb0, emb1, OC,
        cnnx_b, cnny_b, 0);

    k_gemm_f16<0, 0, 1, 0><<<dim3(MT, MT, 1), 256, SM_F16>>>(
        NN_NODE, NN_NODE, OC,
        emb0, emb0, OC,
        emb1, emb1, OC,
        out, out, NN_NODE,
        nullptr, nullptr, 0);
}

// round 9
// speedup vs baseline: 1.1689x; 1.1689x over previous
#include <cuda_runtime.h>
#include <cuda_fp16.h>
#include <math.h>
#include <stdint.h>

#define NN_NODE 10000
#define E_NUM   320000
#define FDIM    256
#define NLAYERS 5
#define OC      128
#define KTOT    (NLAYERS*FDIM)   // 1280

// ---------------- scratch ----------------
__device__ float g_dinv[2][NN_NODE];
__device__ int   g_cnt[2][NN_NODE];
__device__ int   g_rowptr[2][NN_NODE + 1];
__device__ int   g_csr_src[2][E_NUM];
__device__ float g_csr_norm[2][E_NUM];
__device__ __align__(16) __half g_feats[2][(size_t)NN_NODE * KTOT];     // fp16 activations
__device__ __align__(16) __half g_h1[2][(size_t)NN_NODE * FDIM];        // fp16 pre-agg
__device__ __align__(16) __half g_xh[2][(size_t)NN_NODE * FDIM];        // fp16 inputs
__device__ __align__(16) __half g_wt[2][(size_t)NLAYERS * FDIM * FDIM]; // fp16 W^T
__device__ float g_amax[2][NLAYERS];
__device__ float g_atts[2][NLAYERS];
__device__ __align__(16) __half g_weff[2][OC * KTOT];
__device__ __align__(16) __half g_emb[2][(size_t)NN_NODE * OC];

// ---------------- FP16 cp.async GEMM 128x128x32, 3-stage ----------------
// C = A @ B^T.  A [M,K] half rm, B [N,K] half rm. K multiple of 32.
#define MMA_F16(d, a, b) \
  asm volatile("mma.sync.aligned.m16n8k16.row.col.f32.f16.f16.f32 " \
      "{%0,%1,%2,%3}, {%4,%5,%6,%7}, {%8,%9}, {%0,%1,%2,%3};" \
      : "+f"(d[0]), "+f"(d[1]), "+f"(d[2]), "+f"(d[3]) \
      : "r"(a[0]), "r"(a[1]), "r"(a[2]), "r"(a[3]), "r"(b[0]), "r"(b[1]))

__device__ __forceinline__ void cp16(uint32_t d, const void* s, bool p) {
    int sz = p ? 16 : 0;
    asm volatile("cp.async.cg.shared.global [%0], [%1], 16, %2;\n" :: "r"(d), "l"(s), "r"(sz));
}
__device__ __forceinline__ void cp_commit() { asm volatile("cp.async.commit_group;\n"); }
template <int N> __device__ __forceinline__ void cp_wait() {
    asm volatile("cp.async.wait_group %0;\n" :: "n"(N));
}

template <int BIAS, int OUT_HALF, int STREAM_OUT>
__global__ __launch_bounds__(256) void k_gemm_f16(
        int M, int N, int K,
        const __half* __restrict__ A, int lda,
        const __half* __restrict__ B, int ldb,
        void* __restrict__ Cv, int ldc,
        const float* __restrict__ bias) {
    constexpr int STAGES = 3;
    constexpr int LD32 = 20;            // 32 halves + 8 pad = 40 halves = 20 u32
    constexpr int A_ST = 128 * LD32;
    constexpr int B_ST = 128 * LD32;
    extern __shared__ uint32_t smem[];
    uint32_t* As = smem;
    uint32_t* Bs = smem + STAGES * A_ST;

    const int tid = threadIdx.x;
    const int wid = tid >> 5;
    const int lane = tid & 31;
    const int g = lane >> 2, t = lane & 3;
    const int wm = wid >> 1, wn = wid & 1;
    const int i0 = blockIdx.y * 128, j0 = blockIdx.x * 128;

    const int ar = tid >> 1, akc = (tid & 1) * 16;   // row, half-offset

    const bool a_ok = (i0 + ar < M);
    const __half* a_src = A + (size_t)(a_ok ? i0 + ar : M - 1) * lda + akc;
    const bool b_ok = (j0 + ar < N);
    const __half* b_src = B + (size_t)(b_ok ? j0 + ar : N - 1) * ldb + akc;

    uint32_t sa_base = (uint32_t)__cvta_generic_to_shared(&As[ar * LD32 + akc / 2]);
    uint32_t sb_base = (uint32_t)__cvta_generic_to_shared(&Bs[ar * LD32 + akc / 2]);

    auto issue = [&](int s, int k0) {
        uint32_t da = sa_base + s * (A_ST * 4);
        const __half* pa = a_src + k0;
        cp16(da,      pa,     a_ok);
        cp16(da + 16, pa + 8, a_ok);
        uint32_t db = sb_base + s * (B_ST * 4);
        const __half* pb = b_src + k0;
        cp16(db,      pb,     b_ok);
        cp16(db + 16, pb + 8, b_ok);
        cp_commit();
    };

    float acc[2][8][4];
    #pragma unroll
    for (int mt = 0; mt < 2; mt++)
        #pragma unroll
        for (int nt = 0; nt < 8; nt++)
            #pragma unroll
            for (int q = 0; q < 4; q++) acc[mt][nt][q] = 0.0f;

    auto compute = [&](int s) {
        const uint32_t* Ab = As + s * A_ST;
        const uint32_t* Bb = Bs + s * B_ST;
        #pragma unroll
        for (int c = 0; c < 2; c++) {          // two k16 chunks of the k32 tile
            const int base = c * 8;
            uint32_t af[2][4];
            #pragma unroll
            for (int mt = 0; mt < 2; mt++) {
                int r = wm * 32 + mt * 16;
                af[mt][0] = Ab[(r + g) * LD32 + base + t];
                af[mt][1] = Ab[(r + g + 8) * LD32 + base + t];
                af[mt][2] = Ab[(r + g) * LD32 + base + t + 4];
                af[mt][3] = Ab[(r + g + 8) * LD32 + base + t + 4];
            }
            uint32_t bf[8][2];
            #pragma unroll
            for (int nt = 0; nt < 8; nt++) {
                int n = wn * 64 + nt * 8 + g;
                bf[nt][0] = Bb[n * LD32 + base + t];
                bf[nt][1] = Bb[n * LD32 + base + t + 4];
            }
            #pragma unroll
            for (int mt = 0; mt < 2; mt++)
                #pragma unroll
                for (int nt = 0; nt < 8; nt++)
                    MMA_F16(acc[mt][nt], af[mt], bf[nt]);
        }
    };

    const int ktiles = K / 32;
    issue(0, 0);
    if (ktiles > 1) issue(1, 32);
    for (int i = 0; i < ktiles; i++) {
        // committed = min(i+2, ktiles); compute(i) needs group i done.
        // Last iteration: committed == i+1 -> must drain fully.
        if (i < ktiles - 1) cp_wait<STAGES - 2>(); else cp_wait<0>();
        __syncthreads();
        int pf = i + STAGES - 1;
        if (pf < ktiles) issue(pf % STAGES, pf * 32);
        compute(i % STAGES);
    }

    #pragma unroll
    for (int mt = 0; mt < 2; mt++) {
        int r0 = i0 + wm * 32 + mt * 16 + g;
        #pragma unroll
        for (int nt = 0; nt < 8; nt++) {
            int c = j0 + wn * 64 + nt * 8 + 2 * t;
            if (c >= N) continue;
            float bx0 = 0.f, bx1 = 0.f;
            if (BIAS) { bx0 = bias[c]; bx1 = bias[c + 1]; }
            float v00 = acc[mt][nt][0] + bx0, v01 = acc[mt][nt][1] + bx1;
            float v10 = acc[mt][nt][2] + bx0, v11 = acc[mt][nt][3] + bx1;
            if (OUT_HALF) {
                __half* Ch = (__half*)Cv;
                __half2 h0 = __float22half2_rn(make_float2(v00, v01));
                __half2 h1 = __float22half2_rn(make_float2(v10, v11));
                if (r0 < M)     *(__half2*)(Ch + (size_t)r0 * ldc + c) = h0;
                if (r0 + 8 < M) *(__half2*)(Ch + (size_t)(r0 + 8) * ldc + c) = h1;
            } else {
                float* Cf = (float*)Cv;
                float2 p0 = make_float2(v00, v01);
                float2 p1 = make_float2(v10, v11);
                if (STREAM_OUT) {
                    if (r0 < M)     __stcs((float2*)(Cf + (size_t)r0 * ldc + c), p0);
                    if (r0 + 8 < M) __stcs((float2*)(Cf + (size_t)(r0 + 8) * ldc + c), p1);
                } else {
                    if (r0 < M)     *(float2*)(Cf + (size_t)r0 * ldc + c) = p0;
                    if (r0 + 8 < M) *(float2*)(Cf + (size_t)(r0 + 8) * ldc + c) = p1;
                }
            }
        }
    }
}

// ---------------- streams/events/attrs created once ----------------
struct HxRes {
    cudaStream_t s0, s1;
    cudaEvent_t ev_fork, ev_j0, ev_j1;
    HxRes() {
        cudaStreamCreateWithFlags(&s0, cudaStreamNonBlocking);
        cudaStreamCreateWithFlags(&s1, cudaStreamNonBlocking);
        cudaEventCreateWithFlags(&ev_fork, cudaEventDisableTiming);
        cudaEventCreateWithFlags(&ev_j0, cudaEventDisableTiming);
        cudaEventCreateWithFlags(&ev_j1, cudaEventDisableTiming);
        cudaFuncSetAttribute((const void*)k_gemm_f16<0,1,0>, cudaFuncAttributeMaxDynamicSharedMemorySize, 65536);
        cudaFuncSetAttribute((const void*)k_gemm_f16<1,1,0>, cudaFuncAttributeMaxDynamicSharedMemorySize, 65536);
        cudaFuncSetAttribute((const void*)k_gemm_f16<0,0,1>, cudaFuncAttributeMaxDynamicSharedMemorySize, 65536);
    }
};
static HxRes g_hx;

// ---------------- prep kernels (branch-batched, default stream) ----------------
__global__ void k_init() {
    int i = blockIdx.x * blockDim.x + threadIdx.x;
    if (i < NN_NODE) {
        g_dinv[0][i] = 1.0f; g_dinv[1][i] = 1.0f;
        g_cnt[0][i] = 0;     g_cnt[1][i] = 0;
    }
    if (i < NLAYERS) { g_amax[0][i] = 0.0f; g_amax[1][i] = 0.0f; }
}

__global__ void k_halfcpy_b(const float* __restrict__ in0, const float* __restrict__ in1,
                            int n4) {
    int b = blockIdx.y;
    const float* in = b ? in1 : in0;
    __half* out = g_xh[b];
    int i = blockIdx.x * blockDim.x + threadIdx.x;
    if (i < n4) {
        float4 v = ((const float4*)in)[i];
        __half2 h0 = __float22half2_rn(make_float2(v.x, v.y));
        __half2 h1 = __float22half2_rn(make_float2(v.z, v.w));
        ((uint2*)out)[i] = make_uint2(*(uint32_t*)&h0, *(uint32_t*)&h1);
    }
}

// W [L][K][N] f32 -> W^T [L][N][K] half
__global__ void k_halfT_b(const float* __restrict__ in0, const float* __restrict__ in1,
                          int total) {
    int b = blockIdx.y;
    const float* in = b ? in1 : in0;
    __half* out = g_wt[b];
    int idx = blockIdx.x * blockDim.x + threadIdx.x;
    if (idx < total) {
        int l = idx >> 16;
        int rem = idx & 65535;
        int k = rem >> 8, n = rem & 255;
        out[(size_t)l * 65536 + n * 256 + k] = __float2half(in[idx]);
    }
}

__global__ void k_deg_cnt_b(const int* __restrict__ e0, const int* __restrict__ e1,
                            const float* __restrict__ w0, const float* __restrict__ w1) {
    int b = blockIdx.y;
    const int* edges = b ? e1 : e0;
    const float* w = b ? w1 : w0;
    int e = blockIdx.x * blockDim.x + threadIdx.x;
    if (e < E_NUM) {
        int dst = edges[E_NUM + e];
        atomicAdd(&g_dinv[b][dst], w[e]);
        atomicAdd(&g_cnt[b][dst], 1);
    }
}

// scan (+ fused rsqrt); one block per branch
__global__ void k_scan() {
    int b = blockIdx.x;
    __shared__ int wsum[32];
    __shared__ int chunk_base;
    int tid = threadIdx.x, lane = tid & 31, w = tid >> 5;
    if (tid == 0) chunk_base = 0;
    __syncthreads();
    for (int c0 = 0; c0 < NN_NODE; c0 += 1024) {
        int idx = c0 + tid;
        int v = (idx < NN_NODE) ? g_cnt[b][idx] : 0;
        if (idx < NN_NODE) g_dinv[b][idx] = rsqrtf(g_dinv[b][idx]);
        int sc = v;
        #pragma unroll
        for (int off = 1; off < 32; off <<= 1) {
            int u = __shfl_up_sync(0xffffffffu, sc, off);
            if (lane >= off) sc += u;
        }
        if (lane == 31) wsum[w] = sc;
        __syncthreads();
        if (w == 0) {
            int tv = wsum[lane];
            #pragma unroll
            for (int off = 1; off < 32; off <<= 1) {
                int u = __shfl_up_sync(0xffffffffu, tv, off);
                if (lane >= off) tv += u;
            }
            wsum[lane] = tv;
        }
        __syncthreads();
        int total = wsum[31];
        int excl = chunk_base + (w ? wsum[w - 1] : 0) + sc - v;
        if (idx < NN_NODE) { g_rowptr[b][idx] = excl; g_cnt[b][idx] = 0; }
        __syncthreads();
        if (tid == 0) chunk_base += total;
        __syncthreads();
    }
    if (tid == 0) g_rowptr[b][NN_NODE] = chunk_base;
}

__global__ void k_fill_b(const int* __restrict__ e0, const int* __restrict__ e1,
                         const float* __restrict__ w0, const float* __restrict__ w1) {
    int b = blockIdx.y;
    const int* edges = b ? e1 : e0;
    const float* w = b ? w1 : w0;
    int e = blockIdx.x * blockDim.x + threadIdx.x;
    if (e < E_NUM) {
        int s = edges[e];
        int d = edges[E_NUM + e];
        int pos = g_rowptr[b][d] + atomicAdd(&g_cnt[b][d], 1);
        g_csr_src[b][pos] = s;
        g_csr_norm[b][pos] = g_dinv[b][s] * w[e] * g_dinv[b][d];
    }
}

// ---------------- aggregation (half gather, f32 accum, fused bias/relu/max, half out) ----------------
__global__ __launch_bounds__(64) void k_aggregate(const __half* __restrict__ h1, int b,
                                                  const float* __restrict__ bias, int layer) {
    __shared__ float red2[2];
    int v = blockIdx.x;
    int t = threadIdx.x;                 // 0..63, 4 halves each
    const uint2* h1v = (const uint2*)h1;
    float dv = g_dinv[b][v];
    float sw = dv * dv;

    uint2 raw = h1v[(size_t)v * 64 + t];
    float2 a01 = __half22float2(*(__half2*)&raw.x);
    float2 a23 = __half22float2(*(__half2*)&raw.y);
    float4 acc = make_float4(sw * a01.x, sw * a01.y, sw * a23.x, sw * a23.y);

    int e = g_rowptr[b][v];
    int e2 = g_rowptr[b][v + 1];
    const int*   srcs  = g_csr_src[b];
    const float* norms = g_csr_norm[b];
    for (; e + 4 <= e2; e += 4) {
        int u0 = srcs[e], u1 = srcs[e + 1], u2 = srcs[e + 2], u3 = srcs[e + 3];
        float n0 = norms[e], n1 = norms[e + 1], n2 = norms[e + 2], n3 = norms[e + 3];
        uint2 r0 = h1v[(size_t)u0 * 64 + t];
        uint2 r1 = h1v[(size_t)u1 * 64 + t];
        uint2 r2 = h1v[(size_t)u2 * 64 + t];
        uint2 r3 = h1v[(size_t)u3 * 64 + t];
        float2 x0a = __half22float2(*(__half2*)&r0.x), x0b = __half22float2(*(__half2*)&r0.y);
        float2 x1a = __half22float2(*(__half2*)&r1.x), x1b = __half22float2(*(__half2*)&r1.y);
        float2 x2a = __half22float2(*(__half2*)&r2.x), x2b = __half22float2(*(__half2*)&r2.y);
        float2 x3a = __half22float2(*(__half2*)&r3.x), x3b = __half22float2(*(__half2*)&r3.y);
        acc.x += n0 * x0a.x + n1 * x1a.x + n2 * x2a.x + n3 * x3a.x;
        acc.y += n0 * x0a.y + n1 * x1a.y + n2 * x2a.y + n3 * x3a.y;
        acc.z += n0 * x0b.x + n1 * x1b.x + n2 * x2b.x + n3 * x3b.x;
        acc.w += n0 * x0b.y + n1 * x1b.y + n2 * x2b.y + n3 * x3b.y;
    }
    for (; e < e2; e++) {
        float n = norms[e];
        uint2 r = h1v[(size_t)srcs[e] * 64 + t];
        float2 xa = __half22float2(*(__half2*)&r.x), xb = __half22float2(*(__half2*)&r.y);
        acc.x += n * xa.x; acc.y += n * xa.y; acc.z += n * xb.x; acc.w += n * xb.y;
    }
    float4 bv = ((const float4*)bias)[t];
    acc.x = fmaxf(acc.x + bv.x, 0.f);
    acc.y = fmaxf(acc.y + bv.y, 0.f);
    acc.z = fmaxf(acc.z + bv.z, 0.f);
    acc.w = fmaxf(acc.w + bv.w, 0.f);
    __half2 h0 = __float22half2_rn(make_float2(acc.x, acc.y));
    __half2 h1p = __float22half2_rn(make_float2(acc.z, acc.w));
    *(uint2*)&g_feats[b][(size_t)v * KTOT + layer * FDIM + t * 4] =
        make_uint2(*(uint32_t*)&h0, *(uint32_t*)&h1p);

    float m = fmaxf(fmaxf(acc.x, acc.y), fmaxf(acc.z, acc.w));
    #pragma unroll
    for (int off = 16; off > 0; off >>= 1)
        m = fmaxf(m, __shfl_xor_sync(0xffffffffu, m, off));
    if ((t & 31) == 0) red2[t >> 5] = m;
    __syncthreads();
    if (t == 0)
        atomicMax((int*)&g_amax[b][layer], __float_as_int(fmaxf(red2[0], red2[1])));
}

// ---------------- attention FC + effective conv weights ----------------
__global__ void k_attfc(const float* __restrict__ fc1w, const float* __restrict__ fc1b,
                        const float* __restrict__ fc2w, const float* __restrict__ fc2b, int b) {
    if (threadIdx.x == 0 && blockIdx.x == 0) {
        float a[NLAYERS];
        for (int c = 0; c < NLAYERS; c++) a[c] = g_amax[b][c];
        float t[5 * NLAYERS];
        for (int j = 0; j < 5 * NLAYERS; j++) {
            float s = fc1b[j];
            for (int c = 0; c < NLAYERS; c++) s += fc1w[j * NLAYERS + c] * a[c];
            t[j] = fmaxf(s, 0.f);
        }
        for (int c = 0; c < NLAYERS; c++) {
            float s = fc2b[c];
            for (int j = 0; j < 5 * NLAYERS; j++) s += fc2w[c * (5 * NLAYERS) + j] * t[j];
            g_atts[b][c] = 1.0f / (1.0f + expf(-s));
        }
    }
}

__global__ void k_weff(const float* __restrict__ cw, int b) {
    int idx = blockIdx.x * blockDim.x + threadIdx.x;
    if (idx < OC * KTOT) {
        int c = (idx % KTOT) >> 8;
        g_weff[b][idx] = __float2half(cw[idx] * g_atts[b][c]);
    }
}

// ---------------- launch ----------------
extern "C" void kernel_launch(void* const* d_in, const int* in_sizes, int n_in,
                              void* d_out, int out_size) {
    const float* x_m    = (const float*)d_in[0];
    const float* x_d    = (const float*)d_in[1];
    const float* w_m    = (const float*)d_in[2];
    const float* w_d    = (const float*)d_in[3];
    const float* Wx     = (const float*)d_in[4];
    const float* bx     = (const float*)d_in[5];
    const float* Wy     = (const float*)d_in[6];
    const float* by     = (const float*)d_in[7];
    const float* fc1x_w = (const float*)d_in[8];
    const float* fc1x_b = (const float*)d_in[9];
    const float* fc2x_w = (const float*)d_in[10];
    const float* fc2x_b = (const float*)d_in[11];
    const float* fc1y_w = (const float*)d_in[12];
    const float* fc1y_b = (const float*)d_in[13];
    const float* fc2y_w = (const float*)d_in[14];
    const float* fc2y_b = (const float*)d_in[15];
    const float* cnnx_w = (const float*)d_in[16];
    const float* cnnx_b = (const float*)d_in[17];
    const float* cnny_w = (const float*)d_in[18];
    const float* cnny_b = (const float*)d_in[19];
    const int*   edges_m = (const int*)d_in[20];
    const int*   edges_d = (const int*)d_in[21];
    float* out = (float*)d_out;

    __half *p_h1, *p_feats, *p_weff, *p_emb, *p_xh, *p_wt;
    cudaGetSymbolAddress((void**)&p_h1,    g_h1);
    cudaGetSymbolAddress((void**)&p_feats, g_feats);
    cudaGetSymbolAddress((void**)&p_weff,  g_weff);
    cudaGetSymbolAddress((void**)&p_emb,   g_emb);
    cudaGetSymbolAddress((void**)&p_xh,    g_xh);
    cudaGetSymbolAddress((void**)&p_wt,    g_wt);

    const int MT = (NN_NODE + 127) / 128;   // 79
    const int SM_F16 = 3 * (128 * 20 + 128 * 20) * 4;  // 61440

    // batched prep on default stream
    k_init<<<(NN_NODE + 255) / 256, 256>>>();
    k_halfcpy_b<<<dim3((NN_NODE * FDIM / 4 + 255) / 256, 2), 256>>>(x_m, x_d, NN_NODE * FDIM / 4);
    k_halfT_b<<<dim3((NLAYERS * FDIM * FDIM + 255) / 256, 2), 256>>>(Wx, Wy, NLAYERS * FDIM * FDIM);
    k_deg_cnt_b<<<dim3(E_NUM / 256, 2), 256>>>(edges_m, edges_d, w_m, w_d);
    k_scan<<<2, 1024>>>();
    k_fill_b<<<dim3(E_NUM / 256, 2), 256>>>(edges_m, edges_d, w_m, w_d);

    cudaEventRecord(g_hx.ev_fork, 0);
    cudaStreamWaitEvent(g_hx.s0, g_hx.ev_fork, 0);
    cudaStreamWaitEvent(g_hx.s1, g_hx.ev_fork, 0);

    for (int b = 0; b < 2; b++) {
        cudaStream_t st = b ? g_hx.s1 : g_hx.s0;
        const float* bias  = b ? by : bx;
        const float* fc1w  = b ? fc1y_w : fc1x_w;
        const float* fc1b  = b ? fc1y_b : fc1x_b;
        const float* fc2w  = b ? fc2y_w : fc2x_w;
        const float* fc2b  = b ? fc2y_b : fc2x_b;
        const float* cw    = b ? cnny_w : cnnx_w;
        const float* cb    = b ? cnny_b : cnnx_b;
        __half* featsB = p_feats + (size_t)b * NN_NODE * KTOT;
        __half* h1B    = p_h1    + (size_t)b * NN_NODE * FDIM;
        __half* xhB    = p_xh    + (size_t)b * NN_NODE * FDIM;
        __half* wtB    = p_wt    + (size_t)b * NLAYERS * FDIM * FDIM;

        const __half* hin = xhB;
        int lda = FDIM;
        for (int i = 0; i < NLAYERS; i++) {
            k_gemm_f16<0, 1, 0><<<dim3(FDIM / 128, MT), 256, SM_F16, st>>>(
                NN_NODE, FDIM, FDIM, hin, lda, wtB + (size_t)i * FDIM * FDIM, FDIM,
                h1B, FDIM, nullptr);
            k_aggregate<<<NN_NODE, 64, 0, st>>>(h1B, b, bias + (size_t)i * FDIM, i);
            hin = featsB + (size_t)i * FDIM;
            lda = KTOT;
        }

        k_attfc<<<1, 32, 0, st>>>(fc1w, fc1b, fc2w, fc2b, b);
        k_weff<<<(OC * KTOT + 255) / 256, 256, 0, st>>>(cw, b);

        k_gemm_f16<1, 1, 0><<<dim3(1, MT), 256, SM_F16, st>>>(
            NN_NODE, OC, KTOT, featsB, KTOT,
            p_weff + (size_t)b * OC * KTOT, KTOT,
            p_emb + (size_t)b * NN_NODE * OC, OC, cb);
    }

    cudaEventRecord(g_hx.ev_j0, g_hx.s0);
    cudaEventRecord(g_hx.ev_j1, g_hx.s1);
    cudaStreamWaitEvent(0, g_hx.ev_j0, 0);
    cudaStreamWaitEvent(0, g_hx.ev_j1, 0);

    k_gemm_f16<0, 0, 1><<<dim3(MT, MT), 256, SM_F16>>>(
        NN_NODE, NN_NODE, OC,
        p_emb, OC,
        p_emb + (size_t)NN_NODE * OC, OC,
        out, NN_NODE, nullptr);
}

// round 10
// speedup vs baseline: 1.2143x; 1.0389x over previous
#include <cuda_runtime.h>
#include <cuda_fp16.h>
#include <math.h>
#include <stdint.h>

#define NN_NODE 10000
#define E_NUM   320000
#define FDIM    256
#define NLAYERS 5
#define OC      128
#define KTOT    (NLAYERS*FDIM)   // 1280

// ---------------- scratch ----------------
__device__ float g_dinv[2][NN_NODE];
__device__ int   g_cnt[2][NN_NODE];
__device__ int   g_rowptr[2][NN_NODE + 1];
__device__ int   g_csr_src[2][E_NUM];
__device__ float g_csr_norm[2][E_NUM];
__device__ __align__(16) __half g_feats[2][(size_t)NN_NODE * KTOT];     // fp16 activations
__device__ __align__(16) __half g_h1[2][(size_t)NN_NODE * FDIM];        // fp16 pre-agg
__device__ __align__(16) __half g_xh[2][(size_t)NN_NODE * FDIM];        // fp16 inputs
__device__ __align__(16) __half g_wt[2][(size_t)NLAYERS * FDIM * FDIM]; // fp16 W^T
__device__ float g_amax[2][NLAYERS];
__device__ float g_atts[2][NLAYERS];
__device__ __align__(16) __half g_weff[2][OC * KTOT];
__device__ __align__(16) __half g_emb[2][(size_t)NN_NODE * OC];

// ---------------- FP16 cp.async GEMM 128x128x32, 3-stage, optional z-batch ----------------
// C = A @ B^T.  A [M,K] half rm, B [N,K] half rm. K multiple of 32.
#define MMA_F16(d, a, b) \
  asm volatile("mma.sync.aligned.m16n8k16.row.col.f32.f16.f16.f32 " \
      "{%0,%1,%2,%3}, {%4,%5,%6,%7}, {%8,%9}, {%0,%1,%2,%3};" \
      : "+f"(d[0]), "+f"(d[1]), "+f"(d[2]), "+f"(d[3]) \
      : "r"(a[0]), "r"(a[1]), "r"(a[2]), "r"(a[3]), "r"(b[0]), "r"(b[1]))

__device__ __forceinline__ void cp16(uint32_t d, const void* s, bool p) {
    int sz = p ? 16 : 0;
    asm volatile("cp.async.cg.shared.global [%0], [%1], 16, %2;\n" :: "r"(d), "l"(s), "r"(sz));
}
__device__ __forceinline__ void cp_commit() { asm volatile("cp.async.commit_group;\n"); }
template <int N> __device__ __forceinline__ void cp_wait() {
    asm volatile("cp.async.wait_group %0;\n" :: "n"(N));
}

template <int BIAS, int OUT_HALF, int STREAM_OUT>
__global__ __launch_bounds__(256) void k_gemm_f16(
        int M, int N, int K,
        const __half* __restrict__ A0, const __half* __restrict__ A1, int lda,
        const __half* __restrict__ B0, const __half* __restrict__ B1, int ldb,
        void* __restrict__ C0, void* __restrict__ C1, int ldc,
        const float* __restrict__ bias0, const float* __restrict__ bias1) {
    constexpr int STAGES = 3;
    constexpr int LD32 = 20;            // 32 halves + 8 pad = 40 halves = 20 u32
    constexpr int A_ST = 128 * LD32;
    constexpr int B_ST = 128 * LD32;
    extern __shared__ uint32_t smem[];
    uint32_t* As = smem;
    uint32_t* Bs = smem + STAGES * A_ST;

    const int bz = blockIdx.z;
    const __half* A = bz ? A1 : A0;
    const __half* B = bz ? B1 : B0;
    void* Cv = bz ? C1 : C0;
    const float* bias = bz ? bias1 : bias0;

    const int tid = threadIdx.x;
    const int wid = tid >> 5;
    const int lane = tid & 31;
    const int g = lane >> 2, t = lane & 3;
    const int wm = wid >> 1, wn = wid & 1;
    const int i0 = blockIdx.y * 128, j0 = blockIdx.x * 128;

    const int ar = tid >> 1, akc = (tid & 1) * 16;   // row, half-offset

    const bool a_ok = (i0 + ar < M);
    const __half* a_src = A + (size_t)(a_ok ? i0 + ar : M - 1) * lda + akc;
    const bool b_ok = (j0 + ar < N);
    const __half* b_src = B + (size_t)(b_ok ? j0 + ar : N - 1) * ldb + akc;

    uint32_t sa_base = (uint32_t)__cvta_generic_to_shared(&As[ar * LD32 + akc / 2]);
    uint32_t sb_base = (uint32_t)__cvta_generic_to_shared(&Bs[ar * LD32 + akc / 2]);

    auto issue = [&](int s, int k0) {
        uint32_t da = sa_base + s * (A_ST * 4);
        const __half* pa = a_src + k0;
        cp16(da,      pa,     a_ok);
        cp16(da + 16, pa + 8, a_ok);
        uint32_t db = sb_base + s * (B_ST * 4);
        const __half* pb = b_src + k0;
        cp16(db,      pb,     b_ok);
        cp16(db + 16, pb + 8, b_ok);
        cp_commit();
    };

    float acc[2][8][4];
    #pragma unroll
    for (int mt = 0; mt < 2; mt++)
        #pragma unroll
        for (int nt = 0; nt < 8; nt++)
            #pragma unroll
            for (int q = 0; q < 4; q++) acc[mt][nt][q] = 0.0f;

    auto compute = [&](int s) {
        const uint32_t* Ab = As + s * A_ST;
        const uint32_t* Bb = Bs + s * B_ST;
        #pragma unroll
        for (int c = 0; c < 2; c++) {          // two k16 chunks of the k32 tile
            const int base = c * 8;
            uint32_t af[2][4];
            #pragma unroll
            for (int mt = 0; mt < 2; mt++) {
                int r = wm * 32 + mt * 16;
                af[mt][0] = Ab[(r + g) * LD32 + base + t];
                af[mt][1] = Ab[(r + g + 8) * LD32 + base + t];
                af[mt][2] = Ab[(r + g) * LD32 + base + t + 4];
                af[mt][3] = Ab[(r + g + 8) * LD32 + base + t + 4];
            }
            uint32_t bf[8][2];
            #pragma unroll
            for (int nt = 0; nt < 8; nt++) {
                int n = wn * 64 + nt * 8 + g;
                bf[nt][0] = Bb[n * LD32 + base + t];
                bf[nt][1] = Bb[n * LD32 + base + t + 4];
            }
            #pragma unroll
            for (int mt = 0; mt < 2; mt++)
                #pragma unroll
                for (int nt = 0; nt < 8; nt++)
                    MMA_F16(acc[mt][nt], af[mt], bf[nt]);
        }
    };

    const int ktiles = K / 32;
    issue(0, 0);
    if (ktiles > 1) issue(1, 32);
    for (int i = 0; i < ktiles; i++) {
        // committed = min(i+2, ktiles); compute(i) needs group i done.
        // Last iteration: committed == i+1 -> must drain fully.
        if (i < ktiles - 1) cp_wait<STAGES - 2>(); else cp_wait<0>();
        __syncthreads();
        int pf = i + STAGES - 1;
        if (pf < ktiles) issue(pf % STAGES, pf * 32);
        compute(i % STAGES);
    }

    #pragma unroll
    for (int mt = 0; mt < 2; mt++) {
        int r0 = i0 + wm * 32 + mt * 16 + g;
        #pragma unroll
        for (int nt = 0; nt < 8; nt++) {
            int c = j0 + wn * 64 + nt * 8 + 2 * t;
            if (c >= N) continue;
            float bx0 = 0.f, bx1 = 0.f;
            if (BIAS) { bx0 = bias[c]; bx1 = bias[c + 1]; }
            float v00 = acc[mt][nt][0] + bx0, v01 = acc[mt][nt][1] + bx1;
            float v10 = acc[mt][nt][2] + bx0, v11 = acc[mt][nt][3] + bx1;
            if (OUT_HALF) {
                __half* Ch = (__half*)Cv;
                __half2 h0 = __float22half2_rn(make_float2(v00, v01));
                __half2 h1 = __float22half2_rn(make_float2(v10, v11));
                if (r0 < M)     *(__half2*)(Ch + (size_t)r0 * ldc + c) = h0;
                if (r0 + 8 < M) *(__half2*)(Ch + (size_t)(r0 + 8) * ldc + c) = h1;
            } else {
                float* Cf = (float*)Cv;
                float2 p0 = make_float2(v00, v01);
                float2 p1 = make_float2(v10, v11);
                if (STREAM_OUT) {
                    if (r0 < M)     __stcs((float2*)(Cf + (size_t)r0 * ldc + c), p0);
                    if (r0 + 8 < M) __stcs((float2*)(Cf + (size_t)(r0 + 8) * ldc + c), p1);
                } else {
                    if (r0 < M)     *(float2*)(Cf + (size_t)r0 * ldc + c) = p0;
                    if (r0 + 8 < M) *(float2*)(Cf + (size_t)(r0 + 8) * ldc + c) = p1;
                }
            }
        }
    }
}

// ---------------- streams/events/attrs created once ----------------
struct HxRes {
    cudaStream_t s0, s1;
    cudaEvent_t ev_fork, ev_h, ev_csr, ev_j0, ev_j1;
    HxRes() {
        cudaStreamCreateWithFlags(&s0, cudaStreamNonBlocking);
        cudaStreamCreateWithFlags(&s1, cudaStreamNonBlocking);
        cudaEventCreateWithFlags(&ev_fork, cudaEventDisableTiming);
        cudaEventCreateWithFlags(&ev_h,    cudaEventDisableTiming);
        cudaEventCreateWithFlags(&ev_csr,  cudaEventDisableTiming);
        cudaEventCreateWithFlags(&ev_j0,   cudaEventDisableTiming);
        cudaEventCreateWithFlags(&ev_j1,   cudaEventDisableTiming);
        cudaFuncSetAttribute((const void*)k_gemm_f16<0,1,0>, cudaFuncAttributeMaxDynamicSharedMemorySize, 65536);
        cudaFuncSetAttribute((const void*)k_gemm_f16<1,1,0>, cudaFuncAttributeMaxDynamicSharedMemorySize, 65536);
        cudaFuncSetAttribute((const void*)k_gemm_f16<0,0,1>, cudaFuncAttributeMaxDynamicSharedMemorySize, 65536);
    }
};
static HxRes g_hx;

// ---------------- prep kernels ----------------
__global__ void k_init() {
    int i = blockIdx.x * blockDim.x + threadIdx.x;
    if (i < NN_NODE) {
        g_dinv[0][i] = 1.0f; g_dinv[1][i] = 1.0f;
        g_cnt[0][i] = 0;     g_cnt[1][i] = 0;
    }
    if (i < NLAYERS) { g_amax[0][i] = 0.0f; g_amax[1][i] = 0.0f; }
}

__global__ void k_halfcpy_b(const float* __restrict__ in0, const float* __restrict__ in1,
                            int n4) {
    int b = blockIdx.y;
    const float* in = b ? in1 : in0;
    __half* out = g_xh[b];
    int i = blockIdx.x * blockDim.x + threadIdx.x;
    if (i < n4) {
        float4 v = ((const float4*)in)[i];
        __half2 h0 = __float22half2_rn(make_float2(v.x, v.y));
        __half2 h1 = __float22half2_rn(make_float2(v.z, v.w));
        ((uint2*)out)[i] = make_uint2(*(uint32_t*)&h0, *(uint32_t*)&h1);
    }
}

// W [L][K][N] f32 -> W^T [L][N][K] half
__global__ void k_halfT_b(const float* __restrict__ in0, const float* __restrict__ in1,
                          int total) {
    int b = blockIdx.y;
    const float* in = b ? in1 : in0;
    __half* out = g_wt[b];
    int idx = blockIdx.x * blockDim.x + threadIdx.x;
    if (idx < total) {
        int l = idx >> 16;
        int rem = idx & 65535;
        int k = rem >> 8, n = rem & 255;
        out[(size_t)l * 65536 + n * 256 + k] = __float2half(in[idx]);
    }
}

__global__ void k_deg_cnt_b(const int* __restrict__ e0, const int* __restrict__ e1,
                            const float* __restrict__ w0, const float* __restrict__ w1) {
    int b = blockIdx.y;
    const int* edges = b ? e1 : e0;
    const float* w = b ? w1 : w0;
    int e = blockIdx.x * blockDim.x + threadIdx.x;
    if (e < E_NUM) {
        int dst = edges[E_NUM + e];
        atomicAdd(&g_dinv[b][dst], w[e]);
        atomicAdd(&g_cnt[b][dst], 1);
    }
}

// scan (+ fused rsqrt); one block per branch
__global__ void k_scan() {
    int b = blockIdx.x;
    __shared__ int wsum[32];
    __shared__ int chunk_base;
    int tid = threadIdx.x, lane = tid & 31, w = tid >> 5;
    if (tid == 0) chunk_base = 0;
    __syncthreads();
    for (int c0 = 0; c0 < NN_NODE; c0 += 1024) {
        int idx = c0 + tid;
        int v = (idx < NN_NODE) ? g_cnt[b][idx] : 0;
        if (idx < NN_NODE) g_dinv[b][idx] = rsqrtf(g_dinv[b][idx]);
        int sc = v;
        #pragma unroll
        for (int off = 1; off < 32; off <<= 1) {
            int u = __shfl_up_sync(0xffffffffu, sc, off);
            if (lane >= off) sc += u;
        }
        if (lane == 31) wsum[w] = sc;
        __syncthreads();
        if (w == 0) {
            int tv = wsum[lane];
            #pragma unroll
            for (int off = 1; off < 32; off <<= 1) {
                int u = __shfl_up_sync(0xffffffffu, tv, off);
                if (lane >= off) tv += u;
            }
            wsum[lane] = tv;
        }
        __syncthreads();
        int total = wsum[31];
        int excl = chunk_base + (w ? wsum[w - 1] : 0) + sc - v;
        if (idx < NN_NODE) { g_rowptr[b][idx] = excl; g_cnt[b][idx] = 0; }
        __syncthreads();
        if (tid == 0) chunk_base += total;
        __syncthreads();
    }
    if (tid == 0) g_rowptr[b][NN_NODE] = chunk_base;
}

__global__ void k_fill_b(const int* __restrict__ e0, const int* __restrict__ e1,
                         const float* __restrict__ w0, const float* __restrict__ w1) {
    int b = blockIdx.y;
    const int* edges = b ? e1 : e0;
    const float* w = b ? w1 : w0;
    int e = blockIdx.x * blockDim.x + threadIdx.x;
    if (e < E_NUM) {
        int s = edges[e];
        int d = edges[E_NUM + e];
        int pos = g_rowptr[b][d] + atomicAdd(&g_cnt[b][d], 1);
        g_csr_src[b][pos] = s;
        g_csr_norm[b][pos] = g_dinv[b][s] * w[e] * g_dinv[b][d];
    }
}

// ---------------- aggregation (half gather, f32 accum, fused bias/relu/max, half out) ----------------
__global__ __launch_bounds__(64) void k_aggregate(const __half* __restrict__ h1, int b,
                                                  const float* __restrict__ bias, int layer) {
    __shared__ float red2[2];
    int v = blockIdx.x;
    int t = threadIdx.x;                 // 0..63, 4 halves each
    const uint2* h1v = (const uint2*)h1;
    float dv = g_dinv[b][v];
    float sw = dv * dv;

    uint2 raw = h1v[(size_t)v * 64 + t];
    float2 a01 = __half22float2(*(__half2*)&raw.x);
    float2 a23 = __half22float2(*(__half2*)&raw.y);
    float4 acc = make_float4(sw * a01.x, sw * a01.y, sw * a23.x, sw * a23.y);

    int e = g_rowptr[b][v];
    int e2 = g_rowptr[b][v + 1];
    const int*   srcs  = g_csr_src[b];
    const float* norms = g_csr_norm[b];
    for (; e + 4 <= e2; e += 4) {
        int u0 = srcs[e], u1 = srcs[e + 1], u2 = srcs[e + 2], u3 = srcs[e + 3];
        float n0 = norms[e], n1 = norms[e + 1], n2 = norms[e + 2], n3 = norms[e + 3];
        uint2 r0 = h1v[(size_t)u0 * 64 + t];
        uint2 r1 = h1v[(size_t)u1 * 64 + t];
        uint2 r2 = h1v[(size_t)u2 * 64 + t];
        uint2 r3 = h1v[(size_t)u3 * 64 + t];
        float2 x0a = __half22float2(*(__half2*)&r0.x), x0b = __half22float2(*(__half2*)&r0.y);
        float2 x1a = __half22float2(*(__half2*)&r1.x), x1b = __half22float2(*(__half2*)&r1.y);
        float2 x2a = __half22float2(*(__half2*)&r2.x), x2b = __half22float2(*(__half2*)&r2.y);
        float2 x3a = __half22float2(*(__half2*)&r3.x), x3b = __half22float2(*(__half2*)&r3.y);
        acc.x += n0 * x0a.x + n1 * x1a.x + n2 * x2a.x + n3 * x3a.x;
        acc.y += n0 * x0a.y + n1 * x1a.y + n2 * x2a.y + n3 * x3a.y;
        acc.z += n0 * x0b.x + n1 * x1b.x + n2 * x2b.x + n3 * x3b.x;
        acc.w += n0 * x0b.y + n1 * x1b.y + n2 * x2b.y + n3 * x3b.y;
    }
    for (; e < e2; e++) {
        float n = norms[e];
        uint2 r = h1v[(size_t)srcs[e] * 64 + t];
        float2 xa = __half22float2(*(__half2*)&r.x), xb = __half22float2(*(__half2*)&r.y);
        acc.x += n * xa.x; acc.y += n * xa.y; acc.z += n * xb.x; acc.w += n * xb.y;
    }
    float4 bv = ((const float4*)bias)[t];
    acc.x = fmaxf(acc.x + bv.x, 0.f);
    acc.y = fmaxf(acc.y + bv.y, 0.f);
    acc.z = fmaxf(acc.z + bv.z, 0.f);
    acc.w = fmaxf(acc.w + bv.w, 0.f);
    __half2 h0 = __float22half2_rn(make_float2(acc.x, acc.y));
    __half2 h1p = __float22half2_rn(make_float2(acc.z, acc.w));
    *(uint2*)&g_feats[b][(size_t)v * KTOT + layer * FDIM + t * 4] =
        make_uint2(*(uint32_t*)&h0, *(uint32_t*)&h1p);

    float m = fmaxf(fmaxf(acc.x, acc.y), fmaxf(acc.z, acc.w));
    #pragma unroll
    for (int off = 16; off > 0; off >>= 1)
        m = fmaxf(m, __shfl_xor_sync(0xffffffffu, m, off));
    if ((t & 31) == 0) red2[t >> 5] = m;
    __syncthreads();
    if (t == 0)
        atomicMax((int*)&g_amax[b][layer], __float_as_int(fmaxf(red2[0], red2[1])));
}

// ---------------- attention FC + effective conv weights (batched) ----------------
__global__ void k_attfc_b(const float* __restrict__ f1w0, const float* __restrict__ f1b0,
                          const float* __restrict__ f2w0, const float* __restrict__ f2b0,
                          const float* __restrict__ f1w1, const float* __restrict__ f1b1,
                          const float* __restrict__ f2w1, const float* __restrict__ f2b1) {
    int b = blockIdx.x;
    const float* fc1w = b ? f1w1 : f1w0;
    const float* fc1b = b ? f1b1 : f1b0;
    const float* fc2w = b ? f2w1 : f2w0;
    const float* fc2b = b ? f2b1 : f2b0;
    if (threadIdx.x == 0) {
        float a[NLAYERS];
        for (int c = 0; c < NLAYERS; c++) a[c] = g_amax[b][c];
        float t[5 * NLAYERS];
        for (int j = 0; j < 5 * NLAYERS; j++) {
            float s = fc1b[j];
            for (int c = 0; c < NLAYERS; c++) s += fc1w[j * NLAYERS + c] * a[c];
            t[j] = fmaxf(s, 0.f);
        }
        for (int c = 0; c < NLAYERS; c++) {
            float s = fc2b[c];
            for (int j = 0; j < 5 * NLAYERS; j++) s += fc2w[c * (5 * NLAYERS) + j] * t[j];
            g_atts[b][c] = 1.0f / (1.0f + expf(-s));
        }
    }
}

__global__ void k_weff_b(const float* __restrict__ cw0, const float* __restrict__ cw1) {
    int b = blockIdx.y;
    const float* cw = b ? cw1 : cw0;
    int idx = blockIdx.x * blockDim.x + threadIdx.x;
    if (idx < OC * KTOT) {
        int c = (idx % KTOT) >> 8;
        g_weff[b][idx] = __float2half(cw[idx] * g_atts[b][c]);
    }
}

// ---------------- launch ----------------
extern "C" void kernel_launch(void* const* d_in, const int* in_sizes, int n_in,
                              void* d_out, int out_size) {
    const float* x_m    = (const float*)d_in[0];
    const float* x_d    = (const float*)d_in[1];
    const float* w_m    = (const float*)d_in[2];
    const float* w_d    = (const float*)d_in[3];
    const float* Wx     = (const float*)d_in[4];
    const float* bx     = (const float*)d_in[5];
    const float* Wy     = (const float*)d_in[6];
    const float* by     = (const float*)d_in[7];
    const float* fc1x_w = (const float*)d_in[8];
    const float* fc1x_b = (const float*)d_in[9];
    const float* fc2x_w = (const float*)d_in[10];
    const float* fc2x_b = (const float*)d_in[11];
    const float* fc1y_w = (const float*)d_in[12];
    const float* fc1y_b = (const float*)d_in[13];
    const float* fc2y_w = (const float*)d_in[14];
    const float* fc2y_b = (const float*)d_in[15];
    const float* cnnx_w = (const float*)d_in[16];
    const float* cnnx_b = (const float*)d_in[17];
    const float* cnny_w = (const float*)d_in[18];
    const float* cnny_b = (const float*)d_in[19];
    const int*   edges_m = (const int*)d_in[20];
    const int*   edges_d = (const int*)d_in[21];
    float* out = (float*)d_out;

    __half *p_h1, *p_feats, *p_weff, *p_emb, *p_xh, *p_wt;
    cudaGetSymbolAddress((void**)&p_h1,    g_h1);
    cudaGetSymbolAddress((void**)&p_feats, g_feats);
    cudaGetSymbolAddress((void**)&p_weff,  g_weff);
    cudaGetSymbolAddress((void**)&p_emb,   g_emb);
    cudaGetSymbolAddress((void**)&p_xh,    g_xh);
    cudaGetSymbolAddress((void**)&p_wt,    g_wt);

    __half* feats0 = p_feats;
    __half* feats1 = p_feats + (size_t)NN_NODE * KTOT;
    __half* weff0  = p_weff;
    __half* weff1  = p_weff + (size_t)OC * KTOT;
    __half* emb0   = p_emb;
    __half* emb1   = p_emb + (size_t)NN_NODE * OC;

    const int MT = (NN_NODE + 127) / 128;   // 79
    const int SM_F16 = 3 * (128 * 20 + 128 * 20) * 4;  // 61440

    // fork from capture-origin stream
    cudaEventRecord(g_hx.ev_fork, 0);
    cudaStreamWaitEvent(g_hx.s0, g_hx.ev_fork, 0);
    cudaStreamWaitEvent(g_hx.s1, g_hx.ev_fork, 0);

    // s0: conversions (needed by GEMM0 of both branches)
    k_halfcpy_b<<<dim3((NN_NODE * FDIM / 4 + 255) / 256, 2), 256, 0, g_hx.s0>>>(x_m, x_d, NN_NODE * FDIM / 4);
    k_halfT_b<<<dim3((NLAYERS * FDIM * FDIM + 255) / 256, 2), 256, 0, g_hx.s0>>>(Wx, Wy, NLAYERS * FDIM * FDIM);
    cudaEventRecord(g_hx.ev_h, g_hx.s0);

    // s1: CSR build (needed only by aggregates)
    k_init<<<(NN_NODE + 255) / 256, 256, 0, g_hx.s1>>>();
    k_deg_cnt_b<<<dim3(E_NUM / 256, 2), 256, 0, g_hx.s1>>>(edges_m, edges_d, w_m, w_d);
    k_scan<<<2, 1024, 0, g_hx.s1>>>();
    k_fill_b<<<dim3(E_NUM / 256, 2), 256, 0, g_hx.s1>>>(edges_m, edges_d, w_m, w_d);
    cudaEventRecord(g_hx.ev_csr, g_hx.s1);

    // cross deps: s1's GEMM0 needs conversions; s0's first aggregate needs CSR
    cudaStreamWaitEvent(g_hx.s1, g_hx.ev_h, 0);

    for (int b = 0; b < 2; b++) {
        cudaStream_t st = b ? g_hx.s1 : g_hx.s0;
        const float* bias = b ? by : bx;
        __half* featsB = p_feats + (size_t)b * NN_NODE * KTOT;
        __half* h1B    = p_h1    + (size_t)b * NN_NODE * FDIM;
        __half* xhB    = p_xh    + (size_t)b * NN_NODE * FDIM;
        __half* wtB    = p_wt    + (size_t)b * NLAYERS * FDIM * FDIM;

        const __half* hin = xhB;
        int lda = FDIM;
        for (int i = 0; i < NLAYERS; i++) {
            k_gemm_f16<0, 1, 0><<<dim3(FDIM / 128, MT), 256, SM_F16, st>>>(
                NN_NODE, FDIM, FDIM,
                hin, hin, lda,
                wtB + (size_t)i * FDIM * FDIM, wtB + (size_t)i * FDIM * FDIM, FDIM,
                h1B, h1B, FDIM, nullptr, nullptr);
            if (b == 0 && i == 0) cudaStreamWaitEvent(g_hx.s0, g_hx.ev_csr, 0);
            k_aggregate<<<NN_NODE, 64, 0, st>>>(h1B, b, bias + (size_t)i * FDIM, i);
            hin = featsB + (size_t)i * FDIM;
            lda = KTOT;
        }
    }

    // join, then batched tail
    cudaEventRecord(g_hx.ev_j0, g_hx.s0);
    cudaEventRecord(g_hx.ev_j1, g_hx.s1);
    cudaStreamWaitEvent(0, g_hx.ev_j0, 0);
    cudaStreamWaitEvent(0, g_hx.ev_j1, 0);

    k_attfc_b<<<2, 32>>>(fc1x_w, fc1x_b, fc2x_w, fc2x_b,
                         fc1y_w, fc1y_b, fc2y_w, fc2y_b);
    k_weff_b<<<dim3((OC * KTOT + 255) / 256, 2), 256>>>(cnnx_w, cnny_w);

    k_gemm_f16<1, 1, 0><<<dim3(1, MT, 2), 256, SM_F16>>>(
        NN_NODE, OC, KTOT,
        feats0, feats1, KTOT,
        weff0, weff1, KTOT,
        emb0, emb1, OC,
        cnnx_b, cnny_b);

    k_gemm_f16<0, 0, 1><<<dim3(MT, MT, 1), 256, SM_F16>>>(
        NN_NODE, NN_NODE, OC,
        emb0, emb0, OC,
        emb1, emb1, OC,
        out, out, NN_NODE,
        nullptr, nullptr);
}

// round 11
// speedup vs baseline: 1.2671x; 1.0435x over previous
#include <cuda_runtime.h>
#include <cuda_fp16.h>
#include <math.h>
#include <stdint.h>

#define NN_NODE 10000
#define E_NUM   320000
#define FDIM    256
#define NLAYERS 5
#define OC      128
#define KTOT    (NLAYERS*FDIM)   // 1280

// ---------------- scratch ----------------
__device__ float g_dinv[2][NN_NODE];
__device__ int   g_cnt[2][NN_NODE];
__device__ int   g_rowptr[2][NN_NODE + 1];
__device__ int   g_csr_src[2][E_NUM];
__device__ float g_csr_norm[2][E_NUM];
__device__ __align__(16) __half g_feats[2][(size_t)NN_NODE * KTOT];
__device__ __align__(16) __half g_h1[2][(size_t)NN_NODE * FDIM];
__device__ __align__(16) __half g_xh[2][(size_t)NN_NODE * FDIM];
__device__ __align__(16) __half g_wt[2][(size_t)NLAYERS * FDIM * FDIM];
__device__ float g_nodemax[2][NLAYERS][NN_NODE];
__device__ float g_atts[2][NLAYERS];
__device__ __align__(16) __half g_weff[2][OC * KTOT];
__device__ __align__(16) __half g_emb[2][(size_t)NN_NODE * OC];

// ---------------- FP16 cp.async GEMM 128x128x32, 3-stage, optional z-batch ----------------
#define MMA_F16(d, a, b) \
  asm volatile("mma.sync.aligned.m16n8k16.row.col.f32.f16.f16.f32 " \
      "{%0,%1,%2,%3}, {%4,%5,%6,%7}, {%8,%9}, {%0,%1,%2,%3};" \
      : "+f"(d[0]), "+f"(d[1]), "+f"(d[2]), "+f"(d[3]) \
      : "r"(a[0]), "r"(a[1]), "r"(a[2]), "r"(a[3]), "r"(b[0]), "r"(b[1]))

__device__ __forceinline__ void cp16(uint32_t d, const void* s, bool p) {
    int sz = p ? 16 : 0;
    asm volatile("cp.async.cg.shared.global [%0], [%1], 16, %2;\n" :: "r"(d), "l"(s), "r"(sz));
}
__device__ __forceinline__ void cp_commit() { asm volatile("cp.async.commit_group;\n"); }
template <int N> __device__ __forceinline__ void cp_wait() {
    asm volatile("cp.async.wait_group %0;\n" :: "n"(N));
}

template <int BIAS, int OUT_HALF, int STREAM_OUT>
__global__ __launch_bounds__(256) void k_gemm_f16(
        int M, int N, int K,
        const __half* __restrict__ A0, const __half* __restrict__ A1, int lda,
        const __half* __restrict__ B0, const __half* __restrict__ B1, int ldb,
        void* __restrict__ C0, void* __restrict__ C1, int ldc,
        const float* __restrict__ bias0, const float* __restrict__ bias1) {
    constexpr int STAGES = 3;
    constexpr int LD32 = 20;
    constexpr int A_ST = 128 * LD32;
    constexpr int B_ST = 128 * LD32;
    extern __shared__ uint32_t smem[];
    uint32_t* As = smem;
    uint32_t* Bs = smem + STAGES * A_ST;

    const int bz = blockIdx.z;
    const __half* A = bz ? A1 : A0;
    const __half* B = bz ? B1 : B0;
    void* Cv = bz ? C1 : C0;
    const float* bias = bz ? bias1 : bias0;

    const int tid = threadIdx.x;
    const int wid = tid >> 5;
    const int lane = tid & 31;
    const int g = lane >> 2, t = lane & 3;
    const int wm = wid >> 1, wn = wid & 1;
    const int i0 = blockIdx.y * 128, j0 = blockIdx.x * 128;

    const int ar = tid >> 1, akc = (tid & 1) * 16;

    const bool a_ok = (i0 + ar < M);
    const __half* a_src = A + (size_t)(a_ok ? i0 + ar : M - 1) * lda + akc;
    const bool b_ok = (j0 + ar < N);
    const __half* b_src = B + (size_t)(b_ok ? j0 + ar : N - 1) * ldb + akc;

    uint32_t sa_base = (uint32_t)__cvta_generic_to_shared(&As[ar * LD32 + akc / 2]);
    uint32_t sb_base = (uint32_t)__cvta_generic_to_shared(&Bs[ar * LD32 + akc / 2]);

    auto issue = [&](int s, int k0) {
        uint32_t da = sa_base + s * (A_ST * 4);
        const __half* pa = a_src + k0;
        cp16(da,      pa,     a_ok);
        cp16(da + 16, pa + 8, a_ok);
        uint32_t db = sb_base + s * (B_ST * 4);
        const __half* pb = b_src + k0;
        cp16(db,      pb,     b_ok);
        cp16(db + 16, pb + 8, b_ok);
        cp_commit();
    };

    float acc[2][8][4];
    #pragma unroll
    for (int mt = 0; mt < 2; mt++)
        #pragma unroll
        for (int nt = 0; nt < 8; nt++)
            #pragma unroll
            for (int q = 0; q < 4; q++) acc[mt][nt][q] = 0.0f;

    auto compute = [&](int s) {
        const uint32_t* Ab = As + s * A_ST;
        const uint32_t* Bb = Bs + s * B_ST;
        #pragma unroll
        for (int c = 0; c < 2; c++) {
            const int base = c * 8;
            uint32_t af[2][4];
            #pragma unroll
            for (int mt = 0; mt < 2; mt++) {
                int r = wm * 32 + mt * 16;
                af[mt][0] = Ab[(r + g) * LD32 + base + t];
                af[mt][1] = Ab[(r + g + 8) * LD32 + base + t];
                af[mt][2] = Ab[(r + g) * LD32 + base + t + 4];
                af[mt][3] = Ab[(r + g + 8) * LD32 + base + t + 4];
            }
            uint32_t bf[8][2];
            #pragma unroll
            for (int nt = 0; nt < 8; nt++) {
                int n = wn * 64 + nt * 8 + g;
                bf[nt][0] = Bb[n * LD32 + base + t];
                bf[nt][1] = Bb[n * LD32 + base + t + 4];
            }
            #pragma unroll
            for (int mt = 0; mt < 2; mt++)
                #pragma unroll
                for (int nt = 0; nt < 8; nt++)
                    MMA_F16(acc[mt][nt], af[mt], bf[nt]);
        }
    };

    const int ktiles = K / 32;
    issue(0, 0);
    if (ktiles > 1) issue(1, 32);
    for (int i = 0; i < ktiles; i++) {
        if (i < ktiles - 1) cp_wait<STAGES - 2>(); else cp_wait<0>();
        __syncthreads();
        int pf = i + STAGES - 1;
        if (pf < ktiles) issue(pf % STAGES, pf * 32);
        compute(i % STAGES);
    }

    #pragma unroll
    for (int mt = 0; mt < 2; mt++) {
        int r0 = i0 + wm * 32 + mt * 16 + g;
        #pragma unroll
        for (int nt = 0; nt < 8; nt++) {
            int c = j0 + wn * 64 + nt * 8 + 2 * t;
            if (c >= N) continue;
            float bx0 = 0.f, bx1 = 0.f;
            if (BIAS) { bx0 = bias[c]; bx1 = bias[c + 1]; }
            float v00 = acc[mt][nt][0] + bx0, v01 = acc[mt][nt][1] + bx1;
            float v10 = acc[mt][nt][2] + bx0, v11 = acc[mt][nt][3] + bx1;
            if (OUT_HALF) {
                __half* Ch = (__half*)Cv;
                __half2 h0 = __float22half2_rn(make_float2(v00, v01));
                __half2 h1 = __float22half2_rn(make_float2(v10, v11));
                if (r0 < M)     *(__half2*)(Ch + (size_t)r0 * ldc + c) = h0;
                if (r0 + 8 < M) *(__half2*)(Ch + (size_t)(r0 + 8) * ldc + c) = h1;
            } else {
                float* Cf = (float*)Cv;
                float2 p0 = make_float2(v00, v01);
                float2 p1 = make_float2(v10, v11);
                if (STREAM_OUT) {
                    if (r0 < M)     __stcs((float2*)(Cf + (size_t)r0 * ldc + c), p0);
                    if (r0 + 8 < M) __stcs((float2*)(Cf + (size_t)(r0 + 8) * ldc + c), p1);
                } else {
                    if (r0 < M)     *(float2*)(Cf + (size_t)r0 * ldc + c) = p0;
                    if (r0 + 8 < M) *(float2*)(Cf + (size_t)(r0 + 8) * ldc + c) = p1;
                }
            }
        }
    }
}

// ---------------- streams/events/attrs created once ----------------
struct HxRes {
    cudaStream_t s0, s1;
    cudaEvent_t ev_fork, ev_h, ev_csr, ev_j0, ev_j1;
    HxRes() {
        cudaStreamCreateWithFlags(&s0, cudaStreamNonBlocking);
        cudaStreamCreateWithFlags(&s1, cudaStreamNonBlocking);
        cudaEventCreateWithFlags(&ev_fork, cudaEventDisableTiming);
        cudaEventCreateWithFlags(&ev_h,    cudaEventDisableTiming);
        cudaEventCreateWithFlags(&ev_csr,  cudaEventDisableTiming);
        cudaEventCreateWithFlags(&ev_j0,   cudaEventDisableTiming);
        cudaEventCreateWithFlags(&ev_j1,   cudaEventDisableTiming);
        cudaFuncSetAttribute((const void*)k_gemm_f16<0,1,0>, cudaFuncAttributeMaxDynamicSharedMemorySize, 65536);
        cudaFuncSetAttribute((const void*)k_gemm_f16<1,1,0>, cudaFuncAttributeMaxDynamicSharedMemorySize, 65536);
        cudaFuncSetAttribute((const void*)k_gemm_f16<0,0,1>, cudaFuncAttributeMaxDynamicSharedMemorySize, 65536);
    }
};
static HxRes g_hx;

// ---------------- prep kernels ----------------
__global__ void k_init() {
    int i = blockIdx.x * blockDim.x + threadIdx.x;
    if (i < NN_NODE) {
        g_dinv[0][i] = 1.0f; g_dinv[1][i] = 1.0f;
        g_cnt[0][i] = 0;     g_cnt[1][i] = 0;
    }
}

__global__ void k_halfcpy_b(const float* __restrict__ in0, const float* __restrict__ in1,
                            int n4) {
    int b = blockIdx.y;
    const float* in = b ? in1 : in0;
    __half* out = g_xh[b];
    int i = blockIdx.x * blockDim.x + threadIdx.x;
    if (i < n4) {
        float4 v = ((const float4*)in)[i];
        __half2 h0 = __float22half2_rn(make_float2(v.x, v.y));
        __half2 h1 = __float22half2_rn(make_float2(v.z, v.w));
        ((uint2*)out)[i] = make_uint2(*(uint32_t*)&h0, *(uint32_t*)&h1);
    }
}

// W [L][K][N] f32 -> W^T [L][N][K] half
__global__ void k_halfT_b(const float* __restrict__ in0, const float* __restrict__ in1,
                          int total) {
    int b = blockIdx.y;
    const float* in = b ? in1 : in0;
    __half* out = g_wt[b];
    int idx = blockIdx.x * blockDim.x + threadIdx.x;
    if (idx < total) {
        int l = idx >> 16;
        int rem = idx & 65535;
        int k = rem >> 8, n = rem & 255;
        out[(size_t)l * 65536 + n * 256 + k] = __float2half(in[idx]);
    }
}

__global__ void k_deg_cnt_b(const int* __restrict__ e0, const int* __restrict__ e1,
                            const float* __restrict__ w0, const float* __restrict__ w1) {
    int b = blockIdx.y;
    const int* edges = b ? e1 : e0;
    const float* w = b ? w1 : w0;
    int e = blockIdx.x * blockDim.x + threadIdx.x;
    if (e < E_NUM) {
        int dst = edges[E_NUM + e];
        atomicAdd(&g_dinv[b][dst], w[e]);
        atomicAdd(&g_cnt[b][dst], 1);
    }
}

__global__ void k_scan() {
    int b = blockIdx.x;
    __shared__ int wsum[32];
    __shared__ int chunk_base;
    int tid = threadIdx.x, lane = tid & 31, w = tid >> 5;
    if (tid == 0) chunk_base = 0;
    __syncthreads();
    for (int c0 = 0; c0 < NN_NODE; c0 += 1024) {
        int idx = c0 + tid;
        int v = (idx < NN_NODE) ? g_cnt[b][idx] : 0;
        if (idx < NN_NODE) g_dinv[b][idx] = rsqrtf(g_dinv[b][idx]);
        int sc = v;
        #pragma unroll
        for (int off = 1; off < 32; off <<= 1) {
            int u = __shfl_up_sync(0xffffffffu, sc, off);
            if (lane >= off) sc += u;
        }
        if (lane == 31) wsum[w] = sc;
        __syncthreads();
        if (w == 0) {
            int tv = wsum[lane];
            #pragma unroll
            for (int off = 1; off < 32; off <<= 1) {
                int u = __shfl_up_sync(0xffffffffu, tv, off);
                if (lane >= off) tv += u;
            }
            wsum[lane] = tv;
        }
        __syncthreads();
        int total = wsum[31];
        int excl = chunk_base + (w ? wsum[w - 1] : 0) + sc - v;
        if (idx < NN_NODE) { g_rowptr[b][idx] = excl; g_cnt[b][idx] = 0; }
        __syncthreads();
        if (tid == 0) chunk_base += total;
        __syncthreads();
    }
    if (tid == 0) g_rowptr[b][NN_NODE] = chunk_base;
}

__global__ void k_fill_b(const int* __restrict__ e0, const int* __restrict__ e1,
                         const float* __restrict__ w0, const float* __restrict__ w1) {
    int b = blockIdx.y;
    const int* edges = b ? e1 : e0;
    const float* w = b ? w1 : w0;
    int e = blockIdx.x * blockDim.x + threadIdx.x;
    if (e < E_NUM) {
        int s = edges[e];
        int d = edges[E_NUM + e];
        int pos = g_rowptr[b][d] + atomicAdd(&g_cnt[b][d], 1);
        g_csr_src[b][pos] = s;
        g_csr_norm[b][pos] = g_dinv[b][s] * w[e] * g_dinv[b][d];
    }
}

// ---------------- aggregation: warp-per-node, uint4 gathers, no atomics ----------------
__global__ __launch_bounds__(64) void k_aggregate(const __half* __restrict__ h1, int b,
                                                  const float* __restrict__ bias, int layer) {
    const int w = threadIdx.x >> 5;          // warp in block
    const int l = threadIdx.x & 31;          // lane: 8 halves = 1 uint4 per lane
    const int v = blockIdx.x * 2 + w;        // node (grid 5000 * 2 = 10000 exact)
    const uint4* h1v = (const uint4*)h1;     // 32 uint4 per row

    float dv = g_dinv[b][v];
    float sw = dv * dv;
    uint4 raw = h1v[(size_t)v * 32 + l];
    float acc[8];
    {
        float2 c0 = __half22float2(*(__half2*)&raw.x);
        float2 c1 = __half22float2(*(__half2*)&raw.y);
        float2 c2 = __half22float2(*(__half2*)&raw.z);
        float2 c3 = __half22float2(*(__half2*)&raw.w);
        acc[0] = sw * c0.x; acc[1] = sw * c0.y; acc[2] = sw * c1.x; acc[3] = sw * c1.y;
        acc[4] = sw * c2.x; acc[5] = sw * c2.y; acc[6] = sw * c3.x; acc[7] = sw * c3.y;
    }

    int e = g_rowptr[b][v];
    int e2 = g_rowptr[b][v + 1];
    const int*   srcs  = g_csr_src[b];
    const float* norms = g_csr_norm[b];

    auto fma8 = [&](float n, uint4 r) {
        float2 c0 = __half22float2(*(__half2*)&r.x);
        float2 c1 = __half22float2(*(__half2*)&r.y);
        float2 c2 = __half22float2(*(__half2*)&r.z);
        float2 c3 = __half22float2(*(__half2*)&r.w);
        acc[0] += n * c0.x; acc[1] += n * c0.y; acc[2] += n * c1.x; acc[3] += n * c1.y;
        acc[4] += n * c2.x; acc[5] += n * c2.y; acc[6] += n * c3.x; acc[7] += n * c3.y;
    };

    for (; e + 4 <= e2; e += 4) {
        int u0 = srcs[e], u1 = srcs[e + 1], u2 = srcs[e + 2], u3 = srcs[e + 3];
        float n0 = norms[e], n1 = norms[e + 1], n2 = norms[e + 2], n3 = norms[e + 3];
        uint4 r0 = h1v[(size_t)u0 * 32 + l];
        uint4 r1 = h1v[(size_t)u1 * 32 + l];
        uint4 r2 = h1v[(size_t)u2 * 32 + l];
        uint4 r3 = h1v[(size_t)u3 * 32 + l];
        fma8(n0, r0); fma8(n1, r1); fma8(n2, r2); fma8(n3, r3);
    }
    for (; e < e2; e++) fma8(norms[e], h1v[(size_t)srcs[e] * 32 + l]);

    const float4* bf = (const float4*)bias;
    float4 b0 = bf[l * 2], b1 = bf[l * 2 + 1];
    acc[0] = fmaxf(acc[0] + b0.x, 0.f); acc[1] = fmaxf(acc[1] + b0.y, 0.f);
    acc[2] = fmaxf(acc[2] + b0.z, 0.f); acc[3] = fmaxf(acc[3] + b0.w, 0.f);
    acc[4] = fmaxf(acc[4] + b1.x, 0.f); acc[5] = fmaxf(acc[5] + b1.y, 0.f);
    acc[6] = fmaxf(acc[6] + b1.z, 0.f); acc[7] = fmaxf(acc[7] + b1.w, 0.f);

    __half2 h0 = __float22half2_rn(make_float2(acc[0], acc[1]));
    __half2 h1p = __float22half2_rn(make_float2(acc[2], acc[3]));
    __half2 h2 = __float22half2_rn(make_float2(acc[4], acc[5]));
    __half2 h3 = __float22half2_rn(make_float2(acc[6], acc[7]));
    uint4 outv = make_uint4(*(uint32_t*)&h0, *(uint32_t*)&h1p, *(uint32_t*)&h2, *(uint32_t*)&h3);
    *(uint4*)&g_feats[b][(size_t)v * KTOT + layer * FDIM + l * 8] = outv;

    float m = acc[0];
    #pragma unroll
    for (int q = 1; q < 8; q++) m = fmaxf(m, acc[q]);
    #pragma unroll
    for (int off = 16; off > 0; off >>= 1)
        m = fmaxf(m, __shfl_xor_sync(0xffffffffu, m, off));
    if (l == 0) g_nodemax[b][layer][v] = m;
}

// ---------------- attention FC (with node-max reduction) + effective conv weights ----------------
__global__ void k_attfc2(const float* __restrict__ fc1w, const float* __restrict__ fc1b,
                         const float* __restrict__ fc2w, const float* __restrict__ fc2b, int b) {
    __shared__ float red[256];
    __shared__ float amax_s[NLAYERS];
    int tid = threadIdx.x;
    for (int c = 0; c < NLAYERS; c++) {
        float m = 0.f;
        for (int i = tid; i < NN_NODE; i += 256) m = fmaxf(m, g_nodemax[b][c][i]);
        red[tid] = m;
        __syncthreads();
        for (int o = 128; o > 0; o >>= 1) {
            if (tid < o) red[tid] = fmaxf(red[tid], red[tid + o]);
            __syncthreads();
        }
        if (tid == 0) amax_s[c] = red[0];
        __syncthreads();
    }
    if (tid == 0) {
        float t[5 * NLAYERS];
        for (int j = 0; j < 5 * NLAYERS; j++) {
            float s = fc1b[j];
            for (int c = 0; c < NLAYERS; c++) s += fc1w[j * NLAYERS + c] * amax_s[c];
            t[j] = fmaxf(s, 0.f);
        }
        for (int c = 0; c < NLAYERS; c++) {
            float s = fc2b[c];
            for (int j = 0; j < 5 * NLAYERS; j++) s += fc2w[c * (5 * NLAYERS) + j] * t[j];
            g_atts[b][c] = 1.0f / (1.0f + expf(-s));
        }
    }
}

__global__ void k_weff(const float* __restrict__ cw, int b) {
    int idx = blockIdx.x * blockDim.x + threadIdx.x;
    if (idx < OC * KTOT) {
        int c = (idx % KTOT) >> 8;
        g_weff[b][idx] = __float2half(cw[idx] * g_atts[b][c]);
    }
}

// ---------------- launch ----------------
extern "C" void kernel_launch(void* const* d_in, const int* in_sizes, int n_in,
                              void* d_out, int out_size) {
    const float* x_m    = (const float*)d_in[0];
    const float* x_d    = (const float*)d_in[1];
    const float* w_m    = (const float*)d_in[2];
    const float* w_d    = (const float*)d_in[3];
    const float* Wx     = (const float*)d_in[4];
    const float* bx     = (const float*)d_in[5];
    const float* Wy     = (const float*)d_in[6];
    const float* by     = (const float*)d_in[7];
    const float* fc1x_w = (const float*)d_in[8];
    const float* fc1x_b = (const float*)d_in[9];
    const float* fc2x_w = (const float*)d_in[10];
    const float* fc2x_b = (const float*)d_in[11];
    const float* fc1y_w = (const float*)d_in[12];
    const float* fc1y_b = (const float*)d_in[13];
    const float* fc2y_w = (const float*)d_in[14];
    const float* fc2y_b = (const float*)d_in[15];
    const float* cnnx_w = (const float*)d_in[16];
    const float* cnnx_b = (const float*)d_in[17];
    const float* cnny_w = (const float*)d_in[18];
    const float* cnny_b = (const float*)d_in[19];
    const int*   edges_m = (const int*)d_in[20];
    const int*   edges_d = (const int*)d_in[21];
    float* out = (float*)d_out;

    __half *p_h1, *p_feats, *p_weff, *p_emb, *p_xh, *p_wt;
    cudaGetSymbolAddress((void**)&p_h1,    g_h1);
    cudaGetSymbolAddress((void**)&p_feats, g_feats);
    cudaGetSymbolAddress((void**)&p_weff,  g_weff);
    cudaGetSymbolAddress((void**)&p_emb,   g_emb);
    cudaGetSymbolAddress((void**)&p_xh,    g_xh);
    cudaGetSymbolAddress((void**)&p_wt,    g_wt);

    __half* emb0 = p_emb;
    __half* emb1 = p_emb + (size_t)NN_NODE * OC;

    const int MT = (NN_NODE + 127) / 128;   // 79
    const int SM_F16 = 3 * (128 * 20 + 128 * 20) * 4;  // 61440

    // fork from capture-origin stream
    cudaEventRecord(g_hx.ev_fork, 0);
    cudaStreamWaitEvent(g_hx.s0, g_hx.ev_fork, 0);
    cudaStreamWaitEvent(g_hx.s1, g_hx.ev_fork, 0);

    // s0: conversions (needed by GEMM0 of both branches)
    k_halfcpy_b<<<dim3((NN_NODE * FDIM / 4 + 255) / 256, 2), 256, 0, g_hx.s0>>>(x_m, x_d, NN_NODE * FDIM / 4);
    k_halfT_b<<<dim3((NLAYERS * FDIM * FDIM + 255) / 256, 2), 256, 0, g_hx.s0>>>(Wx, Wy, NLAYERS * FDIM * FDIM);
    cudaEventRecord(g_hx.ev_h, g_hx.s0);

    // s1: CSR build (needed only by aggregates)
    k_init<<<(NN_NODE + 255) / 256, 256, 0, g_hx.s1>>>();
    k_deg_cnt_b<<<dim3(E_NUM / 256, 2), 256, 0, g_hx.s1>>>(edges_m, edges_d, w_m, w_d);
    k_scan<<<2, 1024, 0, g_hx.s1>>>();
    k_fill_b<<<dim3(E_NUM / 256, 2), 256, 0, g_hx.s1>>>(edges_m, edges_d, w_m, w_d);
    cudaEventRecord(g_hx.ev_csr, g_hx.s1);

    // cross deps: s1's GEMM0 needs conversions; s0's first aggregate needs CSR
    cudaStreamWaitEvent(g_hx.s1, g_hx.ev_h, 0);

    for (int b = 0; b < 2; b++) {
        cudaStream_t st = b ? g_hx.s1 : g_hx.s0;
        const float* bias  = b ? by : bx;
        const float* fc1w  = b ? fc1y_w : fc1x_w;
        const float* fc1b  = b ? fc1y_b : fc1x_b;
        const float* fc2w  = b ? fc2y_w : fc2x_w;
        const float* fc2b  = b ? fc2y_b : fc2x_b;
        const float* cw    = b ? cnny_w : cnnx_w;
        const float* cb    = b ? cnny_b : cnnx_b;
        __half* featsB = p_feats + (size_t)b * NN_NODE * KTOT;
        __half* h1B    = p_h1    + (size_t)b * NN_NODE * FDIM;
        __half* xhB    = p_xh    + (size_t)b * NN_NODE * FDIM;
        __half* wtB    = p_wt    + (size_t)b * NLAYERS * FDIM * FDIM;
        __half* weffB  = p_weff  + (size_t)b * OC * KTOT;
        __half* embB   = b ? emb1 : emb0;

        const __half* hin = xhB;
        int lda = FDIM;
        for (int i = 0; i < NLAYERS; i++) {
            k_gemm_f16<0, 1, 0><<<dim3(FDIM / 128, MT), 256, SM_F16, st>>>(
                NN_NODE, FDIM, FDIM,
                hin, hin, lda,
                wtB + (size_t)i * FDIM * FDIM, wtB + (size_t)i * FDIM * FDIM, FDIM,
                h1B, h1B, FDIM, nullptr, nullptr);
            if (b == 0 && i == 0) cudaStreamWaitEvent(g_hx.s0, g_hx.ev_csr, 0);
            k_aggregate<<<NN_NODE / 2, 64, 0, st>>>(h1B, b, bias + (size_t)i * FDIM, i);
            hin = featsB + (size_t)i * FDIM;
            lda = KTOT;
        }

        // per-branch tail starts as soon as this branch's layers finish
        k_attfc2<<<1, 256, 0, st>>>(fc1w, fc1b, fc2w, fc2b, b);
        k_weff<<<(OC * KTOT + 255) / 256, 256, 0, st>>>(cw, b);
        k_gemm_f16<1, 1, 0><<<dim3(1, MT, 1), 256, SM_F16, st>>>(
            NN_NODE, OC, KTOT,
            featsB, featsB, KTOT,
            weffB, weffB, KTOT,
            embB, embB, OC,
            cb, cb);
    }

    cudaEventRecord(g_hx.ev_j0, g_hx.s0);
    cudaEventRecord(g_hx.ev_j1, g_hx.s1);
    cudaStreamWaitEvent(0, g_hx.ev_j0, 0);
    cudaStreamWaitEvent(0, g_hx.ev_j1, 0);

    k_gemm_f16<0, 0, 1><<<dim3(MT, MT, 1), 256, SM_F16>>>(
        NN_NODE, NN_NODE, OC,
        emb0, emb0, OC,
        emb1, emb1, OC,
        out, out, NN_NODE,
        nullptr, nullptr);
}